// round 3
// baseline (speedup 1.0000x reference)
#include <cuda_runtime.h>

#define N_SAMP 16384
#define MT 32
#define NT 512
#define NB (N_SAMP / MT)

typedef unsigned long long ull;

__device__ __forceinline__ ull ffma2(ull a, ull b, ull c) {
    ull d;
    asm("fma.rn.f32x2 %0, %1, %2, %3;" : "=l"(d) : "l"(a), "l"(b), "l"(c));
    return d;
}
__device__ __forceinline__ float2 upk(ull v) {
    float2 r;
    asm("mov.b64 {%0, %1}, %2;" : "=f"(r.x), "=f"(r.y) : "l"(v));
    return r;
}
// compact bijection 0..255: pair (h, h+64) -> (2h, 2h+1); (h+128, h+192) -> (128+2h, 128+2h+1)
__device__ __forceinline__ int perm(int p) {
    return ((p & 63) << 1) | ((p >> 6) & 1) | (p & 128);
}

// ---- shared memory layout (float offsets) ----
#define W1T_OFF  0            // w1t[d][perm(p)], pitch 258 : 64*258 = 16512
#define SDUP_OFF 16512        // S duplicated pairs [32][64]x2 = 4096
#define SZ1_OFF  20608        // z1 [32][256] = 8192
#define YDUP_OFF 28800        // ydup/udup/vdup [32][256]x2 = 16384
#define SW2_OFF  45184        // W2 tile [32][258] = 8256 ; reused as grad[32][64]
#define B1D_OFF  53440        // b1 perm layout, 256
#define B2D_OFF  53696        // b2, 256
#define W3_OFF   53952        // 256
#define NN_OFF   54208        // 64 (2 partials per sample)
#define SMEM_FLOATS 54272
#define SMEM_BYTES (SMEM_FLOATS * 4)   // 217088 B

__global__ __launch_bounds__(NT, 1)
void learnerct_fused(const float* __restrict__ S,
                     const float* __restrict__ Sdot,
                     const float* __restrict__ W1,
                     const float* __restrict__ b1,
                     const float* __restrict__ W2,
                     const float* __restrict__ b2,
                     const float* __restrict__ W3,
                     float* __restrict__ out)
{
    extern __shared__ float sm[];
    const int tid = threadIdx.x;
    const int m0  = blockIdx.x * MT;

    // ---------------- staging ----------------
    // W1 [256][64] -> w1t[d][perm(p)]
    #pragma unroll
    for (int it = 0; it < 32; it++) {
        int flat = it * NT + tid;            // 0..16383
        int p = flat >> 6, d = flat & 63;
        sm[W1T_OFF + d * 258 + perm(p)] = W1[flat];
    }
    // S -> duplicated pairs
    #pragma unroll
    for (int it = 0; it < 4; it++) {
        int flat = it * NT + tid;            // 0..2047
        float s = S[m0 * 64 + flat];
        *reinterpret_cast<float2*>(&sm[SDUP_OFF + flat * 2]) = make_float2(s, s);
    }
    if (tid < 256) {
        sm[B1D_OFF + perm(tid)] = b1[tid];
        sm[B2D_OFF + perm(tid)] = b2[tid];
        sm[W3_OFF + tid] = W3[tid];
    }
    __syncthreads();

    const int tm = tid >> 6;   // 0..7
    const int th = tid & 63;   // 0..63
    const int mb = tm * 4;

    ull acc[4][2];

    // ---------------- Phase A: z1 = W1 s + b1 ----------------
    {
        ull i0 = *reinterpret_cast<const ull*>(&sm[B1D_OFF + 2 * th]);
        ull i1 = *reinterpret_cast<const ull*>(&sm[B1D_OFF + 2 * th + 128]);
        #pragma unroll
        for (int i = 0; i < 4; i++) { acc[i][0] = i0; acc[i][1] = i1; }
    }
    #pragma unroll 8
    for (int d2 = 0; d2 < 32; d2++) {
        ulonglong2 sa[4];
        #pragma unroll
        for (int i = 0; i < 4; i++)
            sa[i] = *reinterpret_cast<const ulonglong2*>(&sm[SDUP_OFF + (mb + i) * 128 + d2 * 4]);
        ull b00 = *reinterpret_cast<const ull*>(&sm[W1T_OFF + (2 * d2) * 258 + 2 * th]);
        ull b01 = *reinterpret_cast<const ull*>(&sm[W1T_OFF + (2 * d2) * 258 + 2 * th + 128]);
        ull b10 = *reinterpret_cast<const ull*>(&sm[W1T_OFF + (2 * d2 + 1) * 258 + 2 * th]);
        ull b11 = *reinterpret_cast<const ull*>(&sm[W1T_OFF + (2 * d2 + 1) * 258 + 2 * th + 128]);
        #pragma unroll
        for (int i = 0; i < 4; i++) {
            acc[i][0] = ffma2(sa[i].x, b00, acc[i][0]);
            acc[i][1] = ffma2(sa[i].x, b01, acc[i][1]);
            acc[i][0] = ffma2(sa[i].y, b10, acc[i][0]);
            acc[i][1] = ffma2(sa[i].y, b11, acc[i][1]);
        }
    }
    // epilogue A: store z1 and ydup = {z^2, z^2}
    #pragma unroll
    for (int i = 0; i < 4; i++)
        #pragma unroll
        for (int j2 = 0; j2 < 2; j2++) {
            float2 z = upk(acc[i][j2]);
            int h0 = th + 128 * j2, h1 = h0 + 64;
            int row = mb + i;
            sm[SZ1_OFF + row * 256 + h0] = z.x;
            sm[SZ1_OFF + row * 256 + h1] = z.y;
            float y0 = z.x * z.x, y1v = z.y * z.y;
            *reinterpret_cast<float2*>(&sm[YDUP_OFF + row * 512 + h0 * 2]) = make_float2(y0, y0);
            *reinterpret_cast<float2*>(&sm[YDUP_OFF + row * 512 + h1 * 2]) = make_float2(y1v, y1v);
        }

    // ---------------- Phase B: z2 = W2 y1 + b2 ----------------
    {
        ull i0 = *reinterpret_cast<const ull*>(&sm[B2D_OFF + 2 * th]);
        ull i1 = *reinterpret_cast<const ull*>(&sm[B2D_OFF + 2 * th + 128]);
        #pragma unroll
        for (int i = 0; i < 4; i++) { acc[i][0] = i0; acc[i][1] = i1; }
    }
    for (int kc = 0; kc < 256; kc += 32) {
        __syncthreads();
        #pragma unroll
        for (int it = 0; it < 16; it++) {
            int flat = it * NT + tid;        // 0..8191
            int h = flat >> 5, kk = flat & 31;
            sm[SW2_OFF + kk * 258 + perm(h)] = W2[h * 256 + kc + kk];
        }
        __syncthreads();
        #pragma unroll 8
        for (int k2 = 0; k2 < 16; k2++) {
            ulonglong2 ya[4];
            #pragma unroll
            for (int i = 0; i < 4; i++)
                ya[i] = *reinterpret_cast<const ulonglong2*>(
                    &sm[YDUP_OFF + (mb + i) * 512 + kc * 2 + k2 * 4]);
            ull b00 = *reinterpret_cast<const ull*>(&sm[SW2_OFF + (2 * k2) * 258 + 2 * th]);
            ull b01 = *reinterpret_cast<const ull*>(&sm[SW2_OFF + (2 * k2) * 258 + 2 * th + 128]);
            ull b10 = *reinterpret_cast<const ull*>(&sm[SW2_OFF + (2 * k2 + 1) * 258 + 2 * th]);
            ull b11 = *reinterpret_cast<const ull*>(&sm[SW2_OFF + (2 * k2 + 1) * 258 + 2 * th + 128]);
            #pragma unroll
            for (int i = 0; i < 4; i++) {
                acc[i][0] = ffma2(ya[i].x, b00, acc[i][0]);
                acc[i][1] = ffma2(ya[i].x, b01, acc[i][1]);
                acc[i][0] = ffma2(ya[i].y, b10, acc[i][0]);
                acc[i][1] = ffma2(ya[i].y, b11, acc[i][1]);
            }
        }
    }
    __syncthreads();   // all ydup reads done before overwrite as udup
    // epilogue B: u = 2*w3*z2 (duplicated), nn partials
    {
        float pm[4];
        #pragma unroll
        for (int i = 0; i < 4; i++) pm[i] = 0.0f;
        #pragma unroll
        for (int i = 0; i < 4; i++)
            #pragma unroll
            for (int j2 = 0; j2 < 2; j2++) {
                float2 z2v = upk(acc[i][j2]);
                int h0 = th + 128 * j2, h1 = h0 + 64;
                float w30 = sm[W3_OFF + h0], w31 = sm[W3_OFF + h1];
                float u0 = 2.0f * w30 * z2v.x, u1 = 2.0f * w31 * z2v.y;
                *reinterpret_cast<float2*>(&sm[YDUP_OFF + (mb + i) * 512 + h0 * 2]) = make_float2(u0, u0);
                *reinterpret_cast<float2*>(&sm[YDUP_OFF + (mb + i) * 512 + h1 * 2]) = make_float2(u1, u1);
                pm[i] = fmaf(w30 * z2v.x, z2v.x, pm[i]);
                pm[i] = fmaf(w31 * z2v.y, z2v.y, pm[i]);
            }
        #pragma unroll
        for (int off = 16; off > 0; off >>= 1)
            #pragma unroll
            for (int i = 0; i < 4; i++)
                pm[i] += __shfl_xor_sync(0xffffffffu, pm[i], off);
        if ((tid & 31) == 0) {
            int parity = (tid >> 5) & 1;
            #pragma unroll
            for (int i = 0; i < 4; i++)
                sm[NN_OFF + (mb + i) * 2 + parity] = pm[i];
        }
    }

    // ---------------- Phase D: t = u^T W2 ----------------
    #pragma unroll
    for (int i = 0; i < 4; i++) { acc[i][0] = 0ull; acc[i][1] = 0ull; }
    for (int hc = 0; hc < 256; hc += 32) {
        __syncthreads();
        #pragma unroll
        for (int it = 0; it < 16; it++) {
            int flat = it * NT + tid;
            int hh = flat >> 8, p = flat & 255;
            sm[SW2_OFF + hh * 258 + perm(p)] = W2[(hc + hh) * 256 + p];
        }
        __syncthreads();
        #pragma unroll 8
        for (int h2 = 0; h2 < 16; h2++) {
            ulonglong2 ua[4];
            #pragma unroll
            for (int i = 0; i < 4; i++)
                ua[i] = *reinterpret_cast<const ulonglong2*>(
                    &sm[YDUP_OFF + (mb + i) * 512 + hc * 2 + h2 * 4]);
            ull b00 = *reinterpret_cast<const ull*>(&sm[SW2_OFF + (2 * h2) * 258 + 2 * th]);
            ull b01 = *reinterpret_cast<const ull*>(&sm[SW2_OFF + (2 * h2) * 258 + 2 * th + 128]);
            ull b10 = *reinterpret_cast<const ull*>(&sm[SW2_OFF + (2 * h2 + 1) * 258 + 2 * th]);
            ull b11 = *reinterpret_cast<const ull*>(&sm[SW2_OFF + (2 * h2 + 1) * 258 + 2 * th + 128]);
            #pragma unroll
            for (int i = 0; i < 4; i++) {
                acc[i][0] = ffma2(ua[i].x, b00, acc[i][0]);
                acc[i][1] = ffma2(ua[i].x, b01, acc[i][1]);
                acc[i][0] = ffma2(ua[i].y, b10, acc[i][0]);
                acc[i][1] = ffma2(ua[i].y, b11, acc[i][1]);
            }
        }
    }
    __syncthreads();   // all udup reads done before overwrite as vdup
    // epilogue D: v = t * 2*z1, store duplicated into YDUP region
    #pragma unroll
    for (int i = 0; i < 4; i++)
        #pragma unroll
        for (int j2 = 0; j2 < 2; j2++) {
            float2 t = upk(acc[i][j2]);
            int h0 = th + 128 * j2, h1 = h0 + 64;
            float v0 = t.x * 2.0f * sm[SZ1_OFF + (mb + i) * 256 + h0];
            float v1 = t.y * 2.0f * sm[SZ1_OFF + (mb + i) * 256 + h1];
            *reinterpret_cast<float2*>(&sm[YDUP_OFF + (mb + i) * 512 + h0 * 2]) = make_float2(v0, v0);
            *reinterpret_cast<float2*>(&sm[YDUP_OFF + (mb + i) * 512 + h1 * 2]) = make_float2(v1, v1);
        }
    __syncthreads();

    // ---------------- Phase E: grad = v^T W1 (W1 pairs straight from global/L2) ----------------
    {
        const int sp = tid >> 5;           // 0..15 -> 2 samples each
        const int ms = sp * 2;
        const int dd = (tid & 31) * 2;     // d pair
        ull ga0 = 0ull, ga1 = 0ull;
        #pragma unroll 8
        for (int p = 0; p < 256; p++) {
            ull w2p = *reinterpret_cast<const ull*>(&W1[p * 64 + dd]);   // {W1[p][d], W1[p][d+1]}
            ull v0 = *reinterpret_cast<const ull*>(&sm[YDUP_OFF + ms * 512 + p * 2]);
            ull v1 = *reinterpret_cast<const ull*>(&sm[YDUP_OFF + (ms + 1) * 512 + p * 2]);
            ga0 = ffma2(v0, w2p, ga0);
            ga1 = ffma2(v1, w2p, ga1);
        }
        float2 g0 = upk(ga0), g1 = upk(ga1);
        sm[SW2_OFF + ms * 64 + dd]           = g0.x;
        sm[SW2_OFF + ms * 64 + dd + 1]       = g0.y;
        sm[SW2_OFF + (ms + 1) * 64 + dd]     = g1.x;
        sm[SW2_OFF + (ms + 1) * 64 + dd + 1] = g1.y;
    }
    __syncthreads();

    // ---------------- Final epilogue ----------------
    {
        int m = tid >> 4, q = tid & 15;    // 16 threads per sample
        float c = 0.0f, sd = 0.0f, gd = 0.0f;
        #pragma unroll
        for (int r = 0; r < 4; r++) {
            int d = q + 16 * r;
            float s    = sm[SDUP_OFF + (m * 64 + d) * 2];
            float sdot = Sdot[(m0 + m) * 64 + d];
            c  = fmaf(s, s, c);
            sd = fmaf(s, sdot, sd);
            gd = fmaf(sm[SW2_OFF + m * 64 + d], sdot, gd);
        }
        #pragma unroll
        for (int off = 8; off > 0; off >>= 1) {
            c  += __shfl_xor_sync(0xffffffffu, c,  off);
            sd += __shfl_xor_sync(0xffffffffu, sd, off);
            gd += __shfl_xor_sync(0xffffffffu, gd, off);
        }
        if (q == 0) {
            float nn = sm[NN_OFF + m * 2] + sm[NN_OFF + m * 2 + 1];
            out[m0 + m]              = nn * c;
            out[N_SAMP + m0 + m]     = 2.0f * nn * sd + c * gd;
            out[2 * N_SAMP + m0 + m] = c;
        }
    }
}

extern "C" void kernel_launch(void* const* d_in, const int* in_sizes, int n_in,
                              void* d_out, int out_size)
{
    const float* S    = (const float*)d_in[0];
    const float* Sdot = (const float*)d_in[1];
    const float* W1   = (const float*)d_in[2];
    const float* b1   = (const float*)d_in[3];
    const float* W2   = (const float*)d_in[4];
    const float* b2   = (const float*)d_in[5];
    const float* W3   = (const float*)d_in[6];
    float* out = (float*)d_out;

    cudaFuncSetAttribute(learnerct_fused,
                         cudaFuncAttributeMaxDynamicSharedMemorySize, SMEM_BYTES);
    learnerct_fused<<<NB, NT, SMEM_BYTES>>>(S, Sdot, W1, b1, W2, b2, W3, out);
}

// round 5
// speedup vs baseline: 1.3295x; 1.3295x over previous
#include <cuda_runtime.h>

#define N_SAMP 16384
#define MT 32
#define NT 512
#define NB (N_SAMP / MT)

typedef unsigned long long ull;

__device__ __forceinline__ ull ffma2(ull a, ull b, ull c) {
    ull d;
    asm("fma.rn.f32x2 %0, %1, %2, %3;" : "=l"(d) : "l"(a), "l"(b), "l"(c));
    return d;
}
__device__ __forceinline__ float2 upk(ull v) {
    float2 r;
    asm("mov.b64 {%0, %1}, %2;" : "=f"(r.x), "=f"(r.y) : "l"(v));
    return r;
}
__device__ __forceinline__ ull pk(float lo, float hi) {
    ull r;
    asm("mov.b64 %0, {%1, %2};" : "=l"(r) : "f"(lo), "f"(hi));
    return r;
}

// ---- shared memory layout (float offsets) ----
// TILE occupies floats [0, 16896): 256 rows x 33 ull (A/B/D) or 64 rows x 129 ull (E)
#define SS_OFF   16896        // S plain [32][64] = 2048
#define SZ1_OFF  18944        // z1 [32][256] = 8192
#define SY1_OFF  27136        // y1, later v  [32][256] = 8192
#define SU_OFF   35328        // u  [32][256] = 8192
#define SGR_OFF  43520        // grad [32][64] = 2048
#define SB1_OFF  45568
#define SB2_OFF  45824
#define SW3_OFF  46080
#define SNN_OFF  46336        // 32 samples x 4 warp-partials
#define SMEM_FLOATS 46464
#define SMEM_BYTES (SMEM_FLOATS * 4)   // 185856 B

__global__ __launch_bounds__(NT, 1)
void learnerct_fused(const float* __restrict__ S,
                     const float* __restrict__ Sdot,
                     const float* __restrict__ W1,
                     const float* __restrict__ b1,
                     const float* __restrict__ W2,
                     const float* __restrict__ b2,
                     const float* __restrict__ W3,
                     float* __restrict__ out)
{
    extern __shared__ float sm[];
    ull* TU = reinterpret_cast<ull*>(sm);   // tile at offset 0
    const int tid = threadIdx.x;
    const int m0  = blockIdx.x * MT;

    // ---- stage W1 pair-tile TU[h*33 + dp] = {W1[h][2dp], W1[h][2dp+1]} + S + vecs ----
    #pragma unroll
    for (int it = 0; it < 16; it++) {
        int flat = it * NT + tid;           // 0..8191
        int h = flat >> 5, dp = flat & 31;
        TU[h * 33 + dp] = *reinterpret_cast<const ull*>(&W1[h * 64 + 2 * dp]);
    }
    #pragma unroll
    for (int it = 0; it < 4; it++) {
        int f = it * NT + tid;
        sm[SS_OFF + f] = S[m0 * 64 + f];
    }
    if (tid < 256) {
        sm[SB1_OFF + tid] = b1[tid];
        sm[SB2_OFF + tid] = b2[tid];
        sm[SW3_OFF + tid] = W3[tid];
    }
    __syncthreads();

    const int th  = tid & 127;     // column: th and th+128
    const int tm  = tid >> 7;      // 0..3
    const int mb  = tm * 8;        // 8 samples per thread
    const int c0u = th * 33;
    const int c1u = (th + 128) * 33;

    ull acc[8][2];

    // ================= Phase A: z1 = W1 s + b1 =================
    #pragma unroll
    for (int i = 0; i < 8; i++) { acc[i][0] = 0ull; acc[i][1] = 0ull; }
    #pragma unroll
    for (int k4 = 0; k4 < 16; k4++) {
        ulonglong2 a[8];
        #pragma unroll
        for (int i = 0; i < 8; i++)
            a[i] = *reinterpret_cast<const ulonglong2*>(&sm[SS_OFF + (mb + i) * 64 + k4 * 4]);
        ull b00 = TU[c0u + 2 * k4], b01 = TU[c1u + 2 * k4];
        ull b10 = TU[c0u + 2 * k4 + 1], b11 = TU[c1u + 2 * k4 + 1];
        #pragma unroll
        for (int i = 0; i < 8; i++) {
            acc[i][0] = ffma2(a[i].x, b00, acc[i][0]);
            acc[i][1] = ffma2(a[i].x, b01, acc[i][1]);
            acc[i][0] = ffma2(a[i].y, b10, acc[i][0]);
            acc[i][1] = ffma2(a[i].y, b11, acc[i][1]);
        }
    }
    #pragma unroll
    for (int i = 0; i < 8; i++)
        #pragma unroll
        for (int c = 0; c < 2; c++) {
            float2 t = upk(acc[i][c]);
            int h = th + 128 * c;
            float z = t.x + t.y + sm[SB1_OFF + h];
            sm[SZ1_OFF + (mb + i) * 256 + h] = z;
            sm[SY1_OFF + (mb + i) * 256 + h] = z * z;
        }

    // ================= Phase B: z2 = W2 y1 + b2 =================
    #pragma unroll
    for (int i = 0; i < 8; i++) { acc[i][0] = 0ull; acc[i][1] = 0ull; }
    for (int kc = 0; kc < 256; kc += 64) {
        __syncthreads();
        #pragma unroll
        for (int it = 0; it < 16; it++) {
            int flat = it * NT + tid;
            int h = flat >> 5, kp = flat & 31;
            TU[h * 33 + kp] = *reinterpret_cast<const ull*>(&W2[h * 256 + kc + 2 * kp]);
        }
        __syncthreads();
        #pragma unroll
        for (int k4 = 0; k4 < 16; k4++) {
            ulonglong2 a[8];
            #pragma unroll
            for (int i = 0; i < 8; i++)
                a[i] = *reinterpret_cast<const ulonglong2*>(
                    &sm[SY1_OFF + (mb + i) * 256 + kc + k4 * 4]);
            ull b00 = TU[c0u + 2 * k4], b01 = TU[c1u + 2 * k4];
            ull b10 = TU[c0u + 2 * k4 + 1], b11 = TU[c1u + 2 * k4 + 1];
            #pragma unroll
            for (int i = 0; i < 8; i++) {
                acc[i][0] = ffma2(a[i].x, b00, acc[i][0]);
                acc[i][1] = ffma2(a[i].x, b01, acc[i][1]);
                acc[i][0] = ffma2(a[i].y, b10, acc[i][0]);
                acc[i][1] = ffma2(a[i].y, b11, acc[i][1]);
            }
        }
    }
    // epilogue B: u = 2*w3*z2, nn partials
    {
        float pm[8];
        #pragma unroll
        for (int i = 0; i < 8; i++) pm[i] = 0.0f;
        #pragma unroll
        for (int i = 0; i < 8; i++)
            #pragma unroll
            for (int c = 0; c < 2; c++) {
                float2 t = upk(acc[i][c]);
                int h = th + 128 * c;
                float z2 = t.x + t.y + sm[SB2_OFF + h];
                float w3 = sm[SW3_OFF + h];
                sm[SU_OFF + (mb + i) * 256 + h] = 2.0f * w3 * z2;
                pm[i] = fmaf(w3 * z2, z2, pm[i]);
            }
        #pragma unroll
        for (int off = 16; off > 0; off >>= 1)
            #pragma unroll
            for (int i = 0; i < 8; i++)
                pm[i] += __shfl_xor_sync(0xffffffffu, pm[i], off);
        if ((tid & 31) == 0) {
            int wg = (tid >> 5) & 3;
            #pragma unroll
            for (int i = 0; i < 8; i++)
                sm[SNN_OFF + (mb + i) * 4 + wg] = pm[i];
        }
    }

    // ================= Phase D: t = u^T W2 =================
    #pragma unroll
    for (int i = 0; i < 8; i++) { acc[i][0] = 0ull; acc[i][1] = 0ull; }
    for (int hc = 0; hc < 256; hc += 64) {
        __syncthreads();
        #pragma unroll
        for (int it = 0; it < 16; it++) {
            int flat = it * NT + tid;       // 0..8191
            int p = flat & 255, hp = flat >> 8;   // hp 0..31
            float lo = W2[(hc + 2 * hp) * 256 + p];
            float hi = W2[(hc + 2 * hp + 1) * 256 + p];
            TU[p * 33 + hp] = pk(lo, hi);
        }
        __syncthreads();
        #pragma unroll
        for (int h4 = 0; h4 < 16; h4++) {
            ulonglong2 a[8];
            #pragma unroll
            for (int i = 0; i < 8; i++)
                a[i] = *reinterpret_cast<const ulonglong2*>(
                    &sm[SU_OFF + (mb + i) * 256 + hc + h4 * 4]);
            ull b00 = TU[c0u + 2 * h4], b01 = TU[c1u + 2 * h4];
            ull b10 = TU[c0u + 2 * h4 + 1], b11 = TU[c1u + 2 * h4 + 1];
            #pragma unroll
            for (int i = 0; i < 8; i++) {
                acc[i][0] = ffma2(a[i].x, b00, acc[i][0]);
                acc[i][1] = ffma2(a[i].x, b01, acc[i][1]);
                acc[i][0] = ffma2(a[i].y, b10, acc[i][0]);
                acc[i][1] = ffma2(a[i].y, b11, acc[i][1]);
            }
        }
    }
    __syncthreads();   // D compute done everywhere before overwriting y1/TILE
    // epilogue D: v = t * 2*z1 -> plain into SY1 region
    #pragma unroll
    for (int i = 0; i < 8; i++)
        #pragma unroll
        for (int c = 0; c < 2; c++) {
            float2 t = upk(acc[i][c]);
            int h = th + 128 * c;
            float v = (t.x + t.y) * 2.0f * sm[SZ1_OFF + (mb + i) * 256 + h];
            sm[SY1_OFF + (mb + i) * 256 + h] = v;
        }
    // stage E tile: TU[d*129 + pp] = {W1[2pp][d], W1[2pp+1][d]}
    #pragma unroll
    for (int it = 0; it < 16; it++) {
        int flat = it * NT + tid;           // 0..8191
        int d = flat & 63, pp = flat >> 6;  // pp 0..127
        float lo = W1[(2 * pp) * 64 + d];
        float hi = W1[(2 * pp + 1) * 64 + d];
        TU[d * 129 + pp] = pk(lo, hi);
    }
    __syncthreads();

    // ================= Phase E: grad = v^T W1 =================
    {
        const int d   = tid & 63;
        const int sg  = tid >> 6;    // 0..7
        const int ms  = sg * 4;
        const int du  = d * 129;
        ull ga[4] = {0ull, 0ull, 0ull, 0ull};
        #pragma unroll 8
        for (int p4 = 0; p4 < 64; p4++) {
            ulonglong2 a[4];
            #pragma unroll
            for (int i = 0; i < 4; i++)
                a[i] = *reinterpret_cast<const ulonglong2*>(
                    &sm[SY1_OFF + (ms + i) * 256 + p4 * 4]);
            ull b0 = TU[du + 2 * p4], b1 = TU[du + 2 * p4 + 1];
            #pragma unroll
            for (int i = 0; i < 4; i++) {
                ga[i] = ffma2(a[i].x, b0, ga[i]);
                ga[i] = ffma2(a[i].y, b1, ga[i]);
            }
        }
        #pragma unroll
        for (int i = 0; i < 4; i++) {
            float2 g = upk(ga[i]);
            sm[SGR_OFF + (ms + i) * 64 + d] = g.x + g.y;
        }
    }
    __syncthreads();

    // ================= Final epilogue =================
    {
        int m = tid >> 4, q = tid & 15;     // 16 threads per sample
        float c = 0.0f, sd = 0.0f, gd = 0.0f;
        #pragma unroll
        for (int r = 0; r < 4; r++) {
            int d = q + 16 * r;
            float s    = sm[SS_OFF + m * 64 + d];
            float sdot = Sdot[(m0 + m) * 64 + d];
            c  = fmaf(s, s, c);
            sd = fmaf(s, sdot, sd);
            gd = fmaf(sm[SGR_OFF + m * 64 + d], sdot, gd);
        }
        #pragma unroll
        for (int off = 8; off > 0; off >>= 1) {
            c  += __shfl_xor_sync(0xffffffffu, c,  off);
            sd += __shfl_xor_sync(0xffffffffu, sd, off);
            gd += __shfl_xor_sync(0xffffffffu, gd, off);
        }
        if (q == 0) {
            float nn = sm[SNN_OFF + m * 4] + sm[SNN_OFF + m * 4 + 1]
                     + sm[SNN_OFF + m * 4 + 2] + sm[SNN_OFF + m * 4 + 3];
            out[m0 + m]              = nn * c;
            out[N_SAMP + m0 + m]     = 2.0f * nn * sd + c * gd;
            out[2 * N_SAMP + m0 + m] = c;
        }
    }
}

extern "C" void kernel_launch(void* const* d_in, const int* in_sizes, int n_in,
                              void* d_out, int out_size)
{
    const float* S    = (const float*)d_in[0];
    const float* Sdot = (const float*)d_in[1];
    const float* W1   = (const float*)d_in[2];
    const float* b1   = (const float*)d_in[3];
    const float* W2   = (const float*)d_in[4];
    const float* b2   = (const float*)d_in[5];
    const float* W3   = (const float*)d_in[6];
    float* out = (float*)d_out;

    cudaFuncSetAttribute(learnerct_fused,
                         cudaFuncAttributeMaxDynamicSharedMemorySize, SMEM_BYTES);
    learnerct_fused<<<NB, NT, SMEM_BYTES>>>(S, Sdot, W1, b1, W2, b2, W3, out);
}

// round 7
// speedup vs baseline: 1.3547x; 1.0190x over previous
#include <cuda_runtime.h>

#define N_SAMP 16384
#define MT 32
#define NT 256
#define NB (N_SAMP / MT)

typedef unsigned long long ull;

__device__ __forceinline__ ull ffma2(ull a, ull b, ull c) {
    ull d;
    asm("fma.rn.f32x2 %0, %1, %2, %3;" : "=l"(d) : "l"(a), "l"(b), "l"(c));
    return d;
}
__device__ __forceinline__ float2 upk(ull v) {
    float2 r;
    asm("mov.b64 {%0, %1}, %2;" : "=f"(r.x), "=f"(r.y) : "l"(v));
    return r;
}
__device__ __forceinline__ ull pk(float lo, float hi) {
    ull r;
    asm("mov.b64 %0, {%1, %2};" : "=l"(r) : "f"(lo), "f"(hi));
    return r;
}

// ---- shared memory layout (float offsets) ----
// TILE floats [0, 16896): 256 rows x 33 ull (A/B/D) or 64 rows x 129 ull (E)
#define SS_OFF   16896        // S plain [32][64] = 2048
#define SZ1_OFF  18944        // z1 [32][256] = 8192
#define SY1_OFF  27136        // y1, later v  [32][256] = 8192
#define SU_OFF   35328        // u  [32][256] = 8192
#define SGR_OFF  43520        // grad [32][64] = 2048
#define SB1_OFF  45568
#define SB2_OFF  45824
#define SW3_OFF  46080
#define SNN_OFF  46336        // 32 samples x 8 warp-partials = 256
#define SMEM_FLOATS 46592
#define SMEM_BYTES (SMEM_FLOATS * 4)   // 186368 B

__global__ __launch_bounds__(NT, 1)
void learnerct_fused(const float* __restrict__ S,
                     const float* __restrict__ Sdot,
                     const float* __restrict__ W1,
                     const float* __restrict__ b1,
                     const float* __restrict__ W2,
                     const float* __restrict__ b2,
                     const float* __restrict__ W3,
                     float* __restrict__ out)
{
    extern __shared__ float sm[];
    ull* TU = reinterpret_cast<ull*>(sm);
    const int tid = threadIdx.x;
    const int m0  = blockIdx.x * MT;

    // ---- stage W1 pair-tile TU[h*33 + dp] + S + small vecs ----
    #pragma unroll
    for (int it = 0; it < 32; it++) {
        int flat = it * NT + tid;           // 0..8191
        int h = flat >> 5, dp = flat & 31;
        TU[h * 33 + dp] = *reinterpret_cast<const ull*>(&W1[h * 64 + 2 * dp]);
    }
    #pragma unroll
    for (int it = 0; it < 8; it++) {
        int f = it * NT + tid;
        sm[SS_OFF + f] = S[m0 * 64 + f];
    }
    sm[SB1_OFF + tid] = b1[tid];
    sm[SB2_OFF + tid] = b2[tid];
    sm[SW3_OFF + tid] = W3[tid];
    __syncthreads();

    const int lane = tid & 31;
    const int wid  = tid >> 5;         // 0..7
    const int mi   = lane >> 3;        // 0..3  sample offset
    const int ci   = lane & 7;         // 0..7  column lane
    // thread's 8 samples: s_i = 4*i + mi ; 4 columns: c_j = wid*32 + ci + 8*j
    int colu[4];                       // col*33 (ull index into tile)
    #pragma unroll
    for (int j = 0; j < 4; j++) colu[j] = (wid * 32 + ci + 8 * j) * 33;

    ull acc[8][4];

    // ================= Phase A: z1 = W1 s + b1 =================
    #pragma unroll
    for (int i = 0; i < 8; i++)
        #pragma unroll
        for (int j = 0; j < 4; j++) acc[i][j] = 0ull;
    #pragma unroll
    for (int k4 = 0; k4 < 16; k4++) {
        ulonglong2 a[8];
        #pragma unroll
        for (int i = 0; i < 8; i++)
            a[i] = *reinterpret_cast<const ulonglong2*>(
                &sm[SS_OFF + (4 * i + mi) * 64 + k4 * 4]);
        ull b0[4], b1v[4];
        #pragma unroll
        for (int j = 0; j < 4; j++) {
            b0[j]  = TU[colu[j] + 2 * k4];
            b1v[j] = TU[colu[j] + 2 * k4 + 1];
        }
        #pragma unroll
        for (int i = 0; i < 8; i++)
            #pragma unroll
            for (int j = 0; j < 4; j++) {
                acc[i][j] = ffma2(a[i].x, b0[j], acc[i][j]);
                acc[i][j] = ffma2(a[i].y, b1v[j], acc[i][j]);
            }
    }
    #pragma unroll
    for (int i = 0; i < 8; i++)
        #pragma unroll
        for (int j = 0; j < 4; j++) {
            float2 t = upk(acc[i][j]);
            int s = 4 * i + mi, c = wid * 32 + ci + 8 * j;
            float z = t.x + t.y + sm[SB1_OFF + c];
            sm[SZ1_OFF + s * 256 + c] = z;
            sm[SY1_OFF + s * 256 + c] = z * z;
        }

    // ================= Phase B: z2 = W2 y1 + b2 =================
    #pragma unroll
    for (int i = 0; i < 8; i++)
        #pragma unroll
        for (int j = 0; j < 4; j++) acc[i][j] = 0ull;
    for (int kc = 0; kc < 256; kc += 64) {
        __syncthreads();
        #pragma unroll
        for (int it = 0; it < 32; it++) {
            int flat = it * NT + tid;
            int h = flat >> 5, kp = flat & 31;
            TU[h * 33 + kp] = *reinterpret_cast<const ull*>(&W2[h * 256 + kc + 2 * kp]);
        }
        __syncthreads();
        #pragma unroll
        for (int k4 = 0; k4 < 16; k4++) {
            ulonglong2 a[8];
            #pragma unroll
            for (int i = 0; i < 8; i++)
                a[i] = *reinterpret_cast<const ulonglong2*>(
                    &sm[SY1_OFF + (4 * i + mi) * 256 + kc + k4 * 4]);
            ull b0[4], b1v[4];
            #pragma unroll
            for (int j = 0; j < 4; j++) {
                b0[j]  = TU[colu[j] + 2 * k4];
                b1v[j] = TU[colu[j] + 2 * k4 + 1];
            }
            #pragma unroll
            for (int i = 0; i < 8; i++)
                #pragma unroll
                for (int j = 0; j < 4; j++) {
                    acc[i][j] = ffma2(a[i].x, b0[j], acc[i][j]);
                    acc[i][j] = ffma2(a[i].y, b1v[j], acc[i][j]);
                }
        }
    }
    // epilogue B: u = 2*w3*z2, nn partials
    {
        float pm[8];
        #pragma unroll
        for (int i = 0; i < 8; i++) pm[i] = 0.0f;
        #pragma unroll
        for (int i = 0; i < 8; i++)
            #pragma unroll
            for (int j = 0; j < 4; j++) {
                float2 t = upk(acc[i][j]);
                int s = 4 * i + mi, c = wid * 32 + ci + 8 * j;
                float z2 = t.x + t.y + sm[SB2_OFF + c];
                float w3 = sm[SW3_OFF + c];
                sm[SU_OFF + s * 256 + c] = 2.0f * w3 * z2;
                pm[i] = fmaf(w3 * z2, z2, pm[i]);
            }
        // reduce over the 8 ci-lanes (same samples)
        #pragma unroll
        for (int off = 1; off < 8; off <<= 1)
            #pragma unroll
            for (int i = 0; i < 8; i++)
                pm[i] += __shfl_xor_sync(0xffffffffu, pm[i], off);
        if (ci == 0) {
            #pragma unroll
            for (int i = 0; i < 8; i++)
                sm[SNN_OFF + (4 * i + mi) * 8 + wid] = pm[i];
        }
    }

    // ================= Phase D: t = u^T W2 =================
    #pragma unroll
    for (int i = 0; i < 8; i++)
        #pragma unroll
        for (int j = 0; j < 4; j++) acc[i][j] = 0ull;
    for (int hc = 0; hc < 256; hc += 64) {
        __syncthreads();
        #pragma unroll
        for (int it = 0; it < 32; it++) {
            // hp = it, p = tid : coalesced LDG, TU[p*33 + hp] = {W2[hc+2it][p], W2[hc+2it+1][p]}
            float lo = W2[(hc + 2 * it) * 256 + tid];
            float hi = W2[(hc + 2 * it + 1) * 256 + tid];
            TU[tid * 33 + it] = pk(lo, hi);
        }
        __syncthreads();
        #pragma unroll
        for (int h4 = 0; h4 < 16; h4++) {
            ulonglong2 a[8];
            #pragma unroll
            for (int i = 0; i < 8; i++)
                a[i] = *reinterpret_cast<const ulonglong2*>(
                    &sm[SU_OFF + (4 * i + mi) * 256 + hc + h4 * 4]);
            ull b0[4], b1v[4];
            #pragma unroll
            for (int j = 0; j < 4; j++) {
                b0[j]  = TU[colu[j] + 2 * h4];
                b1v[j] = TU[colu[j] + 2 * h4 + 1];
            }
            #pragma unroll
            for (int i = 0; i < 8; i++)
                #pragma unroll
                for (int j = 0; j < 4; j++) {
                    acc[i][j] = ffma2(a[i].x, b0[j], acc[i][j]);
                    acc[i][j] = ffma2(a[i].y, b1v[j], acc[i][j]);
                }
        }
    }
    __syncthreads();   // D reads done before overwriting y1/TILE
    // epilogue D: v = t * 2*z1 -> into SY1 region
    #pragma unroll
    for (int i = 0; i < 8; i++)
        #pragma unroll
        for (int j = 0; j < 4; j++) {
            float2 t = upk(acc[i][j]);
            int s = 4 * i + mi, c = wid * 32 + ci + 8 * j;
            float v = (t.x + t.y) * 2.0f * sm[SZ1_OFF + s * 256 + c];
            sm[SY1_OFF + s * 256 + c] = v;
        }
    // stage E tile: TU[d*129 + pp] = {W1[2pp][d], W1[2pp+1][d]}
    #pragma unroll
    for (int it = 0; it < 32; it++) {
        int flat = it * NT + tid;           // 0..8191
        int d = flat & 63, pp = flat >> 6;  // pp 0..127
        float lo = W1[(2 * pp) * 64 + d];
        float hi = W1[(2 * pp + 1) * 64 + d];
        TU[d * 129 + pp] = pk(lo, hi);
    }
    __syncthreads();

    // ================= Phase E: grad = v^T W1 =================
    // One d per thread (tid&63), 4 groups x 8 samples; ga halves are even/odd-p
    // partials for the SAME d — summed at the end (R5 scheme).
    {
        const int d  = tid & 63;
        const int ms = (tid >> 6) * 8;     // 0,8,16,24
        const int du = d * 129;
        ull ga[8];
        #pragma unroll
        for (int i = 0; i < 8; i++) ga[i] = 0ull;
        #pragma unroll 16
        for (int p4 = 0; p4 < 64; p4++) {
            ulonglong2 a[8];
            #pragma unroll
            for (int i = 0; i < 8; i++)
                a[i] = *reinterpret_cast<const ulonglong2*>(
                    &sm[SY1_OFF + (ms + i) * 256 + p4 * 4]);
            ull b0 = TU[du + 2 * p4], b1v = TU[du + 2 * p4 + 1];
            #pragma unroll
            for (int i = 0; i < 8; i++) {
                ga[i] = ffma2(a[i].x, b0, ga[i]);
                ga[i] = ffma2(a[i].y, b1v, ga[i]);
            }
        }
        #pragma unroll
        for (int i = 0; i < 8; i++) {
            float2 g = upk(ga[i]);
            sm[SGR_OFF + (ms + i) * 64 + d] = g.x + g.y;
        }
    }
    __syncthreads();

    // ================= Final epilogue =================
    {
        int m = tid >> 3, q = tid & 7;      // 8 threads per sample
        float c = 0.0f, sd = 0.0f, gd = 0.0f;
        #pragma unroll
        for (int r = 0; r < 8; r++) {
            int d = q + 8 * r;
            float s    = sm[SS_OFF + m * 64 + d];
            float sdot = Sdot[(m0 + m) * 64 + d];
            c  = fmaf(s, s, c);
            sd = fmaf(s, sdot, sd);
            gd = fmaf(sm[SGR_OFF + m * 64 + d], sdot, gd);
        }
        #pragma unroll
        for (int off = 4; off > 0; off >>= 1) {
            c  += __shfl_xor_sync(0xffffffffu, c,  off);
            sd += __shfl_xor_sync(0xffffffffu, sd, off);
            gd += __shfl_xor_sync(0xffffffffu, gd, off);
        }
        if (q == 0) {
            float nn = 0.0f;
            #pragma unroll
            for (int w = 0; w < 8; w++) nn += sm[SNN_OFF + m * 8 + w];
            out[m0 + m]              = nn * c;
            out[N_SAMP + m0 + m]     = 2.0f * nn * sd + c * gd;
            out[2 * N_SAMP + m0 + m] = c;
        }
    }
}

extern "C" void kernel_launch(void* const* d_in, const int* in_sizes, int n_in,
                              void* d_out, int out_size)
{
    const float* S    = (const float*)d_in[0];
    const float* Sdot = (const float*)d_in[1];
    const float* W1   = (const float*)d_in[2];
    const float* b1   = (const float*)d_in[3];
    const float* W2   = (const float*)d_in[4];
    const float* b2   = (const float*)d_in[5];
    const float* W3   = (const float*)d_in[6];
    float* out = (float*)d_out;

    cudaFuncSetAttribute(learnerct_fused,
                         cudaFuncAttributeMaxDynamicSharedMemorySize, SMEM_BYTES);
    learnerct_fused<<<NB, NT, SMEM_BYTES>>>(S, Sdot, W1, b1, W2, b2, W3, out);
}

// round 8
// speedup vs baseline: 1.5413x; 1.1377x over previous
#include <cuda_runtime.h>

#define N_SAMP 16384
#define MT 32
#define NT 128
#define NB (N_SAMP / MT)

typedef unsigned long long ull;

__device__ __forceinline__ ull ffma2(ull a, ull b, ull c) {
    ull d;
    asm("fma.rn.f32x2 %0, %1, %2, %3;" : "=l"(d) : "l"(a), "l"(b), "l"(c));
    return d;
}
__device__ __forceinline__ float2 upk(ull v) {
    float2 r;
    asm("mov.b64 {%0, %1}, %2;" : "=f"(r.x), "=f"(r.y) : "l"(v));
    return r;
}
__device__ __forceinline__ ull pk(float lo, float hi) {
    ull r;
    asm("mov.b64 %0, {%1, %2};" : "=l"(r) : "f"(lo), "f"(hi));
    return r;
}

// ---- shared memory layout (float offsets), total 112128 B -> 2 blocks/SM ----
// TILE [0, 8704): 256 rows x 17 ull (32-wide weight chunks) ; E half-tile 64 x 65 ull
#define SS_OFF   8704         // S [32][64] = 2048
#define SZ1_OFF  10752        // z1, later v [32][256] = 8192
#define SYU_OFF  18944        // y1 -> u -> grad region [32][256] = 8192
#define SNN_OFF  27136        // 32 samples x 4 warp partials = 128
#define SB1_OFF  27264
#define SB2_OFF  27520
#define SW3_OFF  27776
#define SMEM_FLOATS 28032
#define SMEM_BYTES (SMEM_FLOATS * 4)

__global__ void __launch_bounds__(NT, 2)
learnerct_fused(const float* __restrict__ S,
                const float* __restrict__ Sdot,
                const float* __restrict__ W1,
                const float* __restrict__ b1,
                const float* __restrict__ W2,
                const float* __restrict__ b2,
                const float* __restrict__ W3,
                float* __restrict__ out)
{
    extern __shared__ float sm[];
    ull* TU = reinterpret_cast<ull*>(sm);
    const int tid = threadIdx.x;
    const int m0  = blockIdx.x * MT;

    // ---- stage S + small vectors ----
    #pragma unroll
    for (int it = 0; it < 16; it++) {
        int f = it * NT + tid;
        sm[SS_OFF + f] = S[m0 * 64 + f];
    }
    #pragma unroll
    for (int it = 0; it < 2; it++) {
        int c = it * NT + tid;
        sm[SB1_OFF + c] = b1[c];
        sm[SB2_OFF + c] = b2[c];
        sm[SW3_OFF + c] = W3[c];
    }

    const int lane = tid & 31;
    const int wid  = tid >> 5;      // 0..3
    const int mi   = lane >> 3;     // 0..3 sample offset
    const int ci   = lane & 7;      // 0..7
    const int cg   = wid * 8 + ci;  // 0..31 column group
    int colu[8];
    #pragma unroll
    for (int j = 0; j < 8; j++) colu[j] = (cg + 32 * j) * 17;

    ull acc[8][8];

    // ================= Phase A: z1 = W1 s + b1 =================
    #pragma unroll
    for (int i = 0; i < 8; i++)
        #pragma unroll
        for (int j = 0; j < 8; j++) acc[i][j] = 0ull;
    for (int kc = 0; kc < 64; kc += 32) {
        if (kc) __syncthreads();
        #pragma unroll
        for (int it = 0; it < 32; it++) {
            int flat = it * NT + tid;          // 0..4095
            int h = flat >> 4, dp = flat & 15;
            TU[h * 17 + dp] = *reinterpret_cast<const ull*>(&W1[h * 64 + kc + 2 * dp]);
        }
        __syncthreads();
        #pragma unroll
        for (int k4 = 0; k4 < 8; k4++) {
            ulonglong2 a[8];
            #pragma unroll
            for (int i = 0; i < 8; i++)
                a[i] = *reinterpret_cast<const ulonglong2*>(
                    &sm[SS_OFF + (4 * i + mi) * 64 + kc + k4 * 4]);
            ull b0[8], b1v[8];
            #pragma unroll
            for (int j = 0; j < 8; j++) {
                b0[j]  = TU[colu[j] + 2 * k4];
                b1v[j] = TU[colu[j] + 2 * k4 + 1];
            }
            #pragma unroll
            for (int i = 0; i < 8; i++)
                #pragma unroll
                for (int j = 0; j < 8; j++) {
                    acc[i][j] = ffma2(a[i].x, b0[j], acc[i][j]);
                    acc[i][j] = ffma2(a[i].y, b1v[j], acc[i][j]);
                }
        }
    }
    // epilogue A: z1 + y1
    #pragma unroll
    for (int i = 0; i < 8; i++)
        #pragma unroll
        for (int j = 0; j < 8; j++) {
            float2 t = upk(acc[i][j]);
            int s = 4 * i + mi, c = cg + 32 * j;
            float z = t.x + t.y + sm[SB1_OFF + c];
            sm[SZ1_OFF + s * 256 + c] = z;
            sm[SYU_OFF + s * 256 + c] = z * z;
        }

    // ================= Phase B: z2 = W2 y1 + b2 =================
    #pragma unroll
    for (int i = 0; i < 8; i++)
        #pragma unroll
        for (int j = 0; j < 8; j++) acc[i][j] = 0ull;
    for (int kc = 0; kc < 256; kc += 32) {
        __syncthreads();
        #pragma unroll
        for (int it = 0; it < 32; it++) {
            int flat = it * NT + tid;
            int h = flat >> 4, kp = flat & 15;
            TU[h * 17 + kp] = *reinterpret_cast<const ull*>(&W2[h * 256 + kc + 2 * kp]);
        }
        __syncthreads();
        #pragma unroll
        for (int k4 = 0; k4 < 8; k4++) {
            ulonglong2 a[8];
            #pragma unroll
            for (int i = 0; i < 8; i++)
                a[i] = *reinterpret_cast<const ulonglong2*>(
                    &sm[SYU_OFF + (4 * i + mi) * 256 + kc + k4 * 4]);
            ull b0[8], b1v[8];
            #pragma unroll
            for (int j = 0; j < 8; j++) {
                b0[j]  = TU[colu[j] + 2 * k4];
                b1v[j] = TU[colu[j] + 2 * k4 + 1];
            }
            #pragma unroll
            for (int i = 0; i < 8; i++)
                #pragma unroll
                for (int j = 0; j < 8; j++) {
                    acc[i][j] = ffma2(a[i].x, b0[j], acc[i][j]);
                    acc[i][j] = ffma2(a[i].y, b1v[j], acc[i][j]);
                }
        }
    }
    __syncthreads();   // all y1 reads done before u overwrites
    // epilogue B: u = 2*w3*z2 (into SYU), nn partials
    {
        float pm[8];
        #pragma unroll
        for (int i = 0; i < 8; i++) pm[i] = 0.0f;
        #pragma unroll
        for (int i = 0; i < 8; i++)
            #pragma unroll
            for (int j = 0; j < 8; j++) {
                float2 t = upk(acc[i][j]);
                int s = 4 * i + mi, c = cg + 32 * j;
                float z2 = t.x + t.y + sm[SB2_OFF + c];
                float w3 = sm[SW3_OFF + c];
                sm[SYU_OFF + s * 256 + c] = 2.0f * w3 * z2;
                pm[i] = fmaf(w3 * z2, z2, pm[i]);
            }
        #pragma unroll
        for (int off = 1; off < 8; off <<= 1)
            #pragma unroll
            for (int i = 0; i < 8; i++)
                pm[i] += __shfl_xor_sync(0xffffffffu, pm[i], off);
        if (ci == 0) {
            #pragma unroll
            for (int i = 0; i < 8; i++)
                sm[SNN_OFF + (4 * i + mi) * 4 + wid] = pm[i];
        }
    }

    // ================= Phase D: t = u^T W2 =================
    #pragma unroll
    for (int i = 0; i < 8; i++)
        #pragma unroll
        for (int j = 0; j < 8; j++) acc[i][j] = 0ull;
    for (int hc = 0; hc < 256; hc += 32) {
        __syncthreads();
        #pragma unroll
        for (int it = 0; it < 32; it++) {
            int flat = it * NT + tid;          // 0..4095
            int hp = flat >> 8, p = flat & 255;
            float lo = W2[(hc + 2 * hp) * 256 + p];
            float hi = W2[(hc + 2 * hp + 1) * 256 + p];
            TU[p * 17 + hp] = pk(lo, hi);
        }
        __syncthreads();
        #pragma unroll
        for (int h4 = 0; h4 < 8; h4++) {
            ulonglong2 a[8];
            #pragma unroll
            for (int i = 0; i < 8; i++)
                a[i] = *reinterpret_cast<const ulonglong2*>(
                    &sm[SYU_OFF + (4 * i + mi) * 256 + hc + h4 * 4]);
            ull b0[8], b1v[8];
            #pragma unroll
            for (int j = 0; j < 8; j++) {
                b0[j]  = TU[colu[j] + 2 * h4];
                b1v[j] = TU[colu[j] + 2 * h4 + 1];
            }
            #pragma unroll
            for (int i = 0; i < 8; i++)
                #pragma unroll
                for (int j = 0; j < 8; j++) {
                    acc[i][j] = ffma2(a[i].x, b0[j], acc[i][j]);
                    acc[i][j] = ffma2(a[i].y, b1v[j], acc[i][j]);
                }
        }
    }
    // epilogue D: v = t * 2*z1 (thread-private cells of SZ1)
    #pragma unroll
    for (int i = 0; i < 8; i++)
        #pragma unroll
        for (int j = 0; j < 8; j++) {
            float2 t = upk(acc[i][j]);
            int s = 4 * i + mi, c = cg + 32 * j;
            float v = (t.x + t.y) * 2.0f * sm[SZ1_OFF + s * 256 + c];
            sm[SZ1_OFF + s * 256 + c] = v;
        }

    // ================= Phase E: grad = v^T W1, 2 K-halves =================
    {
        const int dg = tid & 31;       // d = dg and dg+32
        const int sg = tid >> 5;       // 8 samples: s = sg*8 + i
        ull ga[2][8];
        #pragma unroll
        for (int dd = 0; dd < 2; dd++)
            #pragma unroll
            for (int i = 0; i < 8; i++) ga[dd][i] = 0ull;
        for (int H = 0; H < 2; H++) {
            __syncthreads();   // prior TILE reads + v writes complete
            #pragma unroll
            for (int it = 0; it < 32; it++) {
                int flat = it * NT + tid;        // 0..4095
                int d = flat & 63, pe = flat >> 6;
                int pp = H * 64 + pe;
                float lo = W1[(2 * pp) * 64 + d];
                float hi = W1[(2 * pp + 1) * 64 + d];
                TU[d * 65 + pe] = pk(lo, hi);
            }
            __syncthreads();
            #pragma unroll 8
            for (int pe4 = 0; pe4 < 32; pe4++) {
                ulonglong2 a[8];
                #pragma unroll
                for (int i = 0; i < 8; i++)
                    a[i] = *reinterpret_cast<const ulonglong2*>(
                        &sm[SZ1_OFF + (sg * 8 + i) * 256 + H * 128 + pe4 * 4]);
                ull b0a = TU[dg * 65 + 2 * pe4];
                ull b1a = TU[dg * 65 + 2 * pe4 + 1];
                ull b0b = TU[(dg + 32) * 65 + 2 * pe4];
                ull b1b = TU[(dg + 32) * 65 + 2 * pe4 + 1];
                #pragma unroll
                for (int i = 0; i < 8; i++) {
                    ga[0][i] = ffma2(a[i].x, b0a, ga[0][i]);
                    ga[0][i] = ffma2(a[i].y, b1a, ga[0][i]);
                    ga[1][i] = ffma2(a[i].x, b0b, ga[1][i]);
                    ga[1][i] = ffma2(a[i].y, b1b, ga[1][i]);
                }
            }
        }
        __syncthreads();   // all u reads long done; grad region (SYU) safe to overwrite
        #pragma unroll
        for (int i = 0; i < 8; i++)
            #pragma unroll
            for (int dd = 0; dd < 2; dd++) {
                float2 g = upk(ga[dd][i]);
                sm[SYU_OFF + (sg * 8 + i) * 64 + dg + 32 * dd] = g.x + g.y;
            }
    }
    __syncthreads();

    // ================= Final epilogue =================
    {
        int m = tid >> 2, q = tid & 3;      // 4 threads per sample, 16 d each
        float c = 0.0f, sd = 0.0f, gd = 0.0f;
        #pragma unroll
        for (int r = 0; r < 16; r++) {
            int d = q + 4 * r;
            float s    = sm[SS_OFF + m * 64 + d];
            float sdot = Sdot[(m0 + m) * 64 + d];
            c  = fmaf(s, s, c);
            sd = fmaf(s, sdot, sd);
            gd = fmaf(sm[SYU_OFF + m * 64 + d], sdot, gd);
        }
        #pragma unroll
        for (int off = 2; off > 0; off >>= 1) {
            c  += __shfl_xor_sync(0xffffffffu, c,  off);
            sd += __shfl_xor_sync(0xffffffffu, sd, off);
            gd += __shfl_xor_sync(0xffffffffu, gd, off);
        }
        if (q == 0) {
            float nn = sm[SNN_OFF + m * 4] + sm[SNN_OFF + m * 4 + 1]
                     + sm[SNN_OFF + m * 4 + 2] + sm[SNN_OFF + m * 4 + 3];
            out[m0 + m]              = nn * c;
            out[N_SAMP + m0 + m]     = 2.0f * nn * sd + c * gd;
            out[2 * N_SAMP + m0 + m] = c;
        }
    }
}

extern "C" void kernel_launch(void* const* d_in, const int* in_sizes, int n_in,
                              void* d_out, int out_size)
{
    const float* S    = (const float*)d_in[0];
    const float* Sdot = (const float*)d_in[1];
    const float* W1   = (const float*)d_in[2];
    const float* b1   = (const float*)d_in[3];
    const float* W2   = (const float*)d_in[4];
    const float* b2   = (const float*)d_in[5];
    const float* W3   = (const float*)d_in[6];
    float* out = (float*)d_out;

    cudaFuncSetAttribute(learnerct_fused,
                         cudaFuncAttributeMaxDynamicSharedMemorySize, SMEM_BYTES);
    learnerct_fused<<<NB, NT, SMEM_BYTES>>>(S, Sdot, W1, b1, W2, b2, W3, out);
}

// round 9
// speedup vs baseline: 1.5434x; 1.0014x over previous
#include <cuda_runtime.h>

#define N_SAMP 16384
#define MT 32
#define NT 128
#define NB (N_SAMP / MT)

typedef unsigned long long ull;

__device__ __forceinline__ ull ffma2(ull a, ull b, ull c) {
    ull d;
    asm("fma.rn.f32x2 %0, %1, %2, %3;" : "=l"(d) : "l"(a), "l"(b), "l"(c));
    return d;
}
__device__ __forceinline__ float2 upk(ull v) {
    float2 r;
    asm("mov.b64 {%0, %1}, %2;" : "=f"(r.x), "=f"(r.y) : "l"(v));
    return r;
}
__device__ __forceinline__ ull pk(float lo, float hi) {
    ull r;
    asm("mov.b64 %0, {%1, %2};" : "=l"(r) : "f"(lo), "f"(hi));
    return r;
}

// ---- shared memory layout (float offsets), total 112128 B -> 2 blocks/SM ----
// TILE [0, 8704): 256 rows x 17 ull (32-wide weight chunks) ; E half-tile 64 x 65 ull
#define SS_OFF   8704         // S [32][64] = 2048
#define SZ1_OFF  10752        // z1, later v [32][256] = 8192
#define SYU_OFF  18944        // y1 -> u -> grad region [32][256] = 8192
#define SNN_OFF  27136        // 32 samples x 4 warp partials = 128
#define SB1_OFF  27264
#define SB2_OFF  27520
#define SW3_OFF  27776
#define SMEM_FLOATS 28032
#define SMEM_BYTES (SMEM_FLOATS * 4)

__global__ void __launch_bounds__(NT, 2)
learnerct_fused(const float* __restrict__ S,
                const float* __restrict__ Sdot,
                const float* __restrict__ W1,
                const float* __restrict__ b1,
                const float* __restrict__ W2,
                const float* __restrict__ b2,
                const float* __restrict__ W3,
                float* __restrict__ out)
{
    extern __shared__ float sm[];
    ull* TU = reinterpret_cast<ull*>(sm);
    const int tid = threadIdx.x;
    const int m0  = blockIdx.x * MT;

    // ---- stage S + small vectors ----
    #pragma unroll
    for (int it = 0; it < 16; it++) {
        int f = it * NT + tid;
        sm[SS_OFF + f] = S[m0 * 64 + f];
    }
    #pragma unroll
    for (int it = 0; it < 2; it++) {
        int c = it * NT + tid;
        sm[SB1_OFF + c] = b1[c];
        sm[SB2_OFF + c] = b2[c];
        sm[SW3_OFF + c] = W3[c];
    }

    const int lane = tid & 31;
    const int wid  = tid >> 5;      // 0..3
    const int mi   = lane >> 3;     // 0..3 sample offset
    const int ci   = lane & 7;      // 0..7
    const int cg   = wid * 8 + ci;  // 0..31 column group
    int colu[8];
    #pragma unroll
    for (int j = 0; j < 8; j++) colu[j] = (cg + 32 * j) * 17;

    ull acc[8][8];

    // ================= Phase A: z1 = W1 s + b1 =================
    #pragma unroll
    for (int i = 0; i < 8; i++)
        #pragma unroll
        for (int j = 0; j < 8; j++) acc[i][j] = 0ull;
    for (int kc = 0; kc < 64; kc += 32) {
        if (kc) __syncthreads();
        #pragma unroll
        for (int it = 0; it < 32; it++) {
            int flat = it * NT + tid;          // 0..4095
            int h = flat >> 4, dp = flat & 15;
            TU[h * 17 + dp] = *reinterpret_cast<const ull*>(&W1[h * 64 + kc + 2 * dp]);
        }
        __syncthreads();
        #pragma unroll
        for (int k4 = 0; k4 < 8; k4++) {
            ulonglong2 a[8];
            #pragma unroll
            for (int i = 0; i < 8; i++)
                a[i] = *reinterpret_cast<const ulonglong2*>(
                    &sm[SS_OFF + (4 * i + mi) * 64 + kc + k4 * 4]);
            ull b0[8], b1v[8];
            #pragma unroll
            for (int j = 0; j < 8; j++) {
                b0[j]  = TU[colu[j] + 2 * k4];
                b1v[j] = TU[colu[j] + 2 * k4 + 1];
            }
            #pragma unroll
            for (int i = 0; i < 8; i++)
                #pragma unroll
                for (int j = 0; j < 8; j++) {
                    acc[i][j] = ffma2(a[i].x, b0[j], acc[i][j]);
                    acc[i][j] = ffma2(a[i].y, b1v[j], acc[i][j]);
                }
        }
    }
    // epilogue A: z1 + y1
    #pragma unroll
    for (int i = 0; i < 8; i++)
        #pragma unroll
        for (int j = 0; j < 8; j++) {
            float2 t = upk(acc[i][j]);
            int s = 4 * i + mi, c = cg + 32 * j;
            float z = t.x + t.y + sm[SB1_OFF + c];
            sm[SZ1_OFF + s * 256 + c] = z;
            sm[SYU_OFF + s * 256 + c] = z * z;
        }

    // ================= Phase B: z2 = W2 y1 + b2 =================
    #pragma unroll
    for (int i = 0; i < 8; i++)
        #pragma unroll
        for (int j = 0; j < 8; j++) acc[i][j] = 0ull;
    for (int kc = 0; kc < 256; kc += 32) {
        __syncthreads();
        #pragma unroll
        for (int it = 0; it < 32; it++) {
            int flat = it * NT + tid;
            int h = flat >> 4, kp = flat & 15;
            TU[h * 17 + kp] = *reinterpret_cast<const ull*>(&W2[h * 256 + kc + 2 * kp]);
        }
        __syncthreads();
        #pragma unroll
        for (int k4 = 0; k4 < 8; k4++) {
            ulonglong2 a[8];
            #pragma unroll
            for (int i = 0; i < 8; i++)
                a[i] = *reinterpret_cast<const ulonglong2*>(
                    &sm[SYU_OFF + (4 * i + mi) * 256 + kc + k4 * 4]);
            ull b0[8], b1v[8];
            #pragma unroll
            for (int j = 0; j < 8; j++) {
                b0[j]  = TU[colu[j] + 2 * k4];
                b1v[j] = TU[colu[j] + 2 * k4 + 1];
            }
            #pragma unroll
            for (int i = 0; i < 8; i++)
                #pragma unroll
                for (int j = 0; j < 8; j++) {
                    acc[i][j] = ffma2(a[i].x, b0[j], acc[i][j]);
                    acc[i][j] = ffma2(a[i].y, b1v[j], acc[i][j]);
                }
        }
    }
    __syncthreads();   // all y1 reads done before u overwrites
    // epilogue B: u = 2*w3*z2 (into SYU), nn partials
    {
        float pm[8];
        #pragma unroll
        for (int i = 0; i < 8; i++) pm[i] = 0.0f;
        #pragma unroll
        for (int i = 0; i < 8; i++)
            #pragma unroll
            for (int j = 0; j < 8; j++) {
                float2 t = upk(acc[i][j]);
                int s = 4 * i + mi, c = cg + 32 * j;
                float z2 = t.x + t.y + sm[SB2_OFF + c];
                float w3 = sm[SW3_OFF + c];
                sm[SYU_OFF + s * 256 + c] = 2.0f * w3 * z2;
                pm[i] = fmaf(w3 * z2, z2, pm[i]);
            }
        #pragma unroll
        for (int off = 1; off < 8; off <<= 1)
            #pragma unroll
            for (int i = 0; i < 8; i++)
                pm[i] += __shfl_xor_sync(0xffffffffu, pm[i], off);
        if (ci == 0) {
            #pragma unroll
            for (int i = 0; i < 8; i++)
                sm[SNN_OFF + (4 * i + mi) * 4 + wid] = pm[i];
        }
    }

    // ================= Phase D: t = u^T W2 =================
    #pragma unroll
    for (int i = 0; i < 8; i++)
        #pragma unroll
        for (int j = 0; j < 8; j++) acc[i][j] = 0ull;
    for (int hc = 0; hc < 256; hc += 32) {
        __syncthreads();
        #pragma unroll
        for (int it = 0; it < 32; it++) {
            int flat = it * NT + tid;          // 0..4095
            int hp = flat >> 8, p = flat & 255;
            float lo = W2[(hc + 2 * hp) * 256 + p];
            float hi = W2[(hc + 2 * hp + 1) * 256 + p];
            TU[p * 17 + hp] = pk(lo, hi);
        }
        __syncthreads();
        #pragma unroll
        for (int h4 = 0; h4 < 8; h4++) {
            ulonglong2 a[8];
            #pragma unroll
            for (int i = 0; i < 8; i++)
                a[i] = *reinterpret_cast<const ulonglong2*>(
                    &sm[SYU_OFF + (4 * i + mi) * 256 + hc + h4 * 4]);
            ull b0[8], b1v[8];
            #pragma unroll
            for (int j = 0; j < 8; j++) {
                b0[j]  = TU[colu[j] + 2 * h4];
                b1v[j] = TU[colu[j] + 2 * h4 + 1];
            }
            #pragma unroll
            for (int i = 0; i < 8; i++)
                #pragma unroll
                for (int j = 0; j < 8; j++) {
                    acc[i][j] = ffma2(a[i].x, b0[j], acc[i][j]);
                    acc[i][j] = ffma2(a[i].y, b1v[j], acc[i][j]);
                }
        }
    }
    // epilogue D: v = t * 2*z1 (thread-private cells of SZ1)
    #pragma unroll
    for (int i = 0; i < 8; i++)
        #pragma unroll
        for (int j = 0; j < 8; j++) {
            float2 t = upk(acc[i][j]);
            int s = 4 * i + mi, c = cg + 32 * j;
            float v = (t.x + t.y) * 2.0f * sm[SZ1_OFF + s * 256 + c];
            sm[SZ1_OFF + s * 256 + c] = v;
        }

    // ================= Phase E: grad = v^T W1, 2 K-halves =================
    {
        const int dg = tid & 31;       // d = dg and dg+32
        const int sg = tid >> 5;       // 8 samples: s = sg*8 + i
        ull ga[2][8];
        #pragma unroll
        for (int dd = 0; dd < 2; dd++)
            #pragma unroll
            for (int i = 0; i < 8; i++) ga[dd][i] = 0ull;
        for (int H = 0; H < 2; H++) {
            __syncthreads();   // prior TILE reads + v writes complete
            #pragma unroll
            for (int it = 0; it < 32; it++) {
                int flat = it * NT + tid;        // 0..4095
                int d = flat & 63, pe = flat >> 6;
                int pp = H * 64 + pe;
                float lo = W1[(2 * pp) * 64 + d];
                float hi = W1[(2 * pp + 1) * 64 + d];
                TU[d * 65 + pe] = pk(lo, hi);
            }
            __syncthreads();
            #pragma unroll 8
            for (int pe4 = 0; pe4 < 32; pe4++) {
                ulonglong2 a[8];
                #pragma unroll
                for (int i = 0; i < 8; i++)
                    a[i] = *reinterpret_cast<const ulonglong2*>(
                        &sm[SZ1_OFF + (sg * 8 + i) * 256 + H * 128 + pe4 * 4]);
                ull b0a = TU[dg * 65 + 2 * pe4];
                ull b1a = TU[dg * 65 + 2 * pe4 + 1];
                ull b0b = TU[(dg + 32) * 65 + 2 * pe4];
                ull b1b = TU[(dg + 32) * 65 + 2 * pe4 + 1];
                #pragma unroll
                for (int i = 0; i < 8; i++) {
                    ga[0][i] = ffma2(a[i].x, b0a, ga[0][i]);
                    ga[0][i] = ffma2(a[i].y, b1a, ga[0][i]);
                    ga[1][i] = ffma2(a[i].x, b0b, ga[1][i]);
                    ga[1][i] = ffma2(a[i].y, b1b, ga[1][i]);
                }
            }
        }
        __syncthreads();   // all u reads long done; grad region (SYU) safe to overwrite
        #pragma unroll
        for (int i = 0; i < 8; i++)
            #pragma unroll
            for (int dd = 0; dd < 2; dd++) {
                float2 g = upk(ga[dd][i]);
                sm[SYU_OFF + (sg * 8 + i) * 64 + dg + 32 * dd] = g.x + g.y;
            }
    }
    __syncthreads();

    // ================= Final epilogue =================
    {
        int m = tid >> 2, q = tid & 3;      // 4 threads per sample, 16 d each
        float c = 0.0f, sd = 0.0f, gd = 0.0f;
        #pragma unroll
        for (int r = 0; r < 16; r++) {
            int d = q + 4 * r;
            float s    = sm[SS_OFF + m * 64 + d];
            float sdot = Sdot[(m0 + m) * 64 + d];
            c  = fmaf(s, s, c);
            sd = fmaf(s, sdot, sd);
            gd = fmaf(sm[SYU_OFF + m * 64 + d], sdot, gd);
        }
        #pragma unroll
        for (int off = 2; off > 0; off >>= 1) {
            c  += __shfl_xor_sync(0xffffffffu, c,  off);
            sd += __shfl_xor_sync(0xffffffffu, sd, off);
            gd += __shfl_xor_sync(0xffffffffu, gd, off);
        }
        if (q == 0) {
            float nn = sm[SNN_OFF + m * 4] + sm[SNN_OFF + m * 4 + 1]
                     + sm[SNN_OFF + m * 4 + 2] + sm[SNN_OFF + m * 4 + 3];
            out[m0 + m]              = nn * c;
            out[N_SAMP + m0 + m]     = 2.0f * nn * sd + c * gd;
            out[2 * N_SAMP + m0 + m] = c;
        }
    }
}

extern "C" void kernel_launch(void* const* d_in, const int* in_sizes, int n_in,
                              void* d_out, int out_size)
{
    const float* S    = (const float*)d_in[0];
    const float* Sdot = (const float*)d_in[1];
    const float* W1   = (const float*)d_in[2];
    const float* b1   = (const float*)d_in[3];
    const float* W2   = (const float*)d_in[4];
    const float* b2   = (const float*)d_in[5];
    const float* W3   = (const float*)d_in[6];
    float* out = (float*)d_out;

    cudaFuncSetAttribute(learnerct_fused,
                         cudaFuncAttributeMaxDynamicSharedMemorySize, SMEM_BYTES);
    learnerct_fused<<<NB, NT, SMEM_BYTES>>>(S, Sdot, W1, b1, W2, b2, W3, out);
}

// round 11
// speedup vs baseline: 2.5392x; 1.6452x over previous
#include <cuda_runtime.h>
#include <cuda_bf16.h>
#include <cstdint>

#define N_SAMP 16384
#define M_CTA  64
#define NCTA   (N_SAMP / M_CTA)   // 256
#define NT     256

// word (uint32/float) offsets in dynamic smem
#define ZSo 0        // z1 f32 [64][258]
#define AHo 16512    // ACT hi bf16-pairs [64][132]
#define ALo 24960    // ACT lo
#define WHo 33408    // W tile hi: [256][36] (A/B/D) or [64][132] (E)
#define WLo 42624    // W tile lo
#define B1o 51840
#define B2o 52096
#define W3o 52352
#define NNo 52608    // [64][2]
#define GDo 52736    // [64][2]
#define SMEM_WORDS 52864
#define SMEM_BYTES (SMEM_WORDS * 4)   // 211456

#define PA 132   // ACT pitch (words)  — 132 % 32 == 4
#define PW 36    // weight tile pitch  — 36 % 32 == 4
#define PE 132   // E-phase W1T pitch

__device__ __forceinline__ void mma_bf16(float d[4], const uint32_t a[4],
                                         uint32_t b0, uint32_t b1) {
    asm volatile(
        "mma.sync.aligned.m16n8k16.row.col.f32.bf16.bf16.f32 "
        "{%0,%1,%2,%3}, {%4,%5,%6,%7}, {%8,%9}, {%0,%1,%2,%3};"
        : "+f"(d[0]), "+f"(d[1]), "+f"(d[2]), "+f"(d[3])
        : "r"(a[0]), "r"(a[1]), "r"(a[2]), "r"(a[3]), "r"(b0), "r"(b1));
}

__device__ __forceinline__ void cvt_pair(float x0, float x1, uint32_t& hp, uint32_t& lp) {
    __nv_bfloat16 h0 = __float2bfloat16_rn(x0);
    __nv_bfloat16 h1 = __float2bfloat16_rn(x1);
    float l0 = x0 - __bfloat162float(h0);
    float l1 = x1 - __bfloat162float(h1);
    __nv_bfloat162 hv(h0, h1), lv(__float2bfloat16_rn(l0), __float2bfloat16_rn(l1));
    hp = *reinterpret_cast<uint32_t*>(&hv);
    lp = *reinterpret_cast<uint32_t*>(&lv);
}

__global__ void __launch_bounds__(NT, 1)
learnerct_mma(const float* __restrict__ S, const float* __restrict__ Sdot,
              const float* __restrict__ W1, const float* __restrict__ b1,
              const float* __restrict__ W2, const float* __restrict__ b2,
              const float* __restrict__ W3, float* __restrict__ out)
{
    extern __shared__ uint32_t sw[];
    float* sf = reinterpret_cast<float*>(sw);
    const int tid = threadIdx.x, lane = tid & 31, wid = tid >> 5;
    const int t4 = lane >> 2, q = lane & 3;
    const int mt = wid & 3, nh = wid >> 2;
    const int rA = mt * 16 + t4;          // fragment row (and rA+8)
    const int m0 = blockIdx.x * M_CTA;

    // ---- stage S -> ACT kpairs 0..31 (hi/lo) ----
    #pragma unroll
    for (int it = 0; it < 8; it++) {
        int combo = it * 8 + wid;
        int r = (combo & 7) * 8 + t4, kp = (combo >> 3) * 4 + q;
        float2 x = *reinterpret_cast<const float2*>(&S[(m0 + r) * 64 + 2 * kp]);
        uint32_t hp, lp; cvt_pair(x.x, x.y, hp, lp);
        sw[AHo + r * PA + kp] = hp;
        sw[ALo + r * PA + kp] = lp;
    }
    // ---- stage W1 [256 n][32 kp] ----
    #pragma unroll
    for (int it = 0; it < 32; it++) {
        int combo = it * 8 + wid;
        int n = (combo & 31) * 8 + t4, kp = (combo >> 5) * 4 + q;
        float2 x = *reinterpret_cast<const float2*>(&W1[n * 64 + 2 * kp]);
        uint32_t hp, lp; cvt_pair(x.x, x.y, hp, lp);
        sw[WHo + n * PW + kp] = hp;
        sw[WLo + n * PW + kp] = lp;
    }
    sf[B1o + tid] = b1[tid];
    sf[B2o + tid] = b2[tid];
    sf[W3o + tid] = W3[tid];
    __syncthreads();

    float dacc[16][4];
    uint32_t ah[4], al[4];

    // ================= Phase A: z1 = S W1^T + b1 =================
    #pragma unroll
    for (int nt = 0; nt < 16; nt++)
        #pragma unroll
        for (int j = 0; j < 4; j++) dacc[nt][j] = 0.0f;
    #pragma unroll
    for (int ks = 0; ks < 4; ks++) {
        int kb = ks * 8;
        ah[0] = sw[AHo + rA * PA + kb + q];       ah[1] = sw[AHo + (rA + 8) * PA + kb + q];
        ah[2] = sw[AHo + rA * PA + kb + q + 4];   ah[3] = sw[AHo + (rA + 8) * PA + kb + q + 4];
        al[0] = sw[ALo + rA * PA + kb + q];       al[1] = sw[ALo + (rA + 8) * PA + kb + q];
        al[2] = sw[ALo + rA * PA + kb + q + 4];   al[3] = sw[ALo + (rA + 8) * PA + kb + q + 4];
        #pragma unroll
        for (int nt = 0; nt < 16; nt++) {
            int nrow = (nh * 16 + nt) * 8 + t4;
            uint32_t bh0 = sw[WHo + nrow * PW + kb + q], bh1 = sw[WHo + nrow * PW + kb + q + 4];
            uint32_t bl0 = sw[WLo + nrow * PW + kb + q], bl1 = sw[WLo + nrow * PW + kb + q + 4];
            mma_bf16(dacc[nt], ah, bh0, bh1);
            mma_bf16(dacc[nt], ah, bl0, bl1);
            mma_bf16(dacc[nt], al, bh0, bh1);
        }
    }
    __syncthreads();     // all S reads done before y1 overwrites ACT
    // ep-A: z1 -> ZS, y1 = z1^2 -> ACT
    #pragma unroll
    for (int nt = 0; nt < 16; nt++) {
        int c0 = (nh * 16 + nt) * 8 + 2 * q, cp = (nh * 16 + nt) * 4 + q;
        float z0 = dacc[nt][0] + sf[B1o + c0], z1 = dacc[nt][1] + sf[B1o + c0 + 1];
        float z2 = dacc[nt][2] + sf[B1o + c0], z3 = dacc[nt][3] + sf[B1o + c0 + 1];
        *reinterpret_cast<float2*>(&sf[ZSo + rA * 258 + c0])       = make_float2(z0, z1);
        *reinterpret_cast<float2*>(&sf[ZSo + (rA + 8) * 258 + c0]) = make_float2(z2, z3);
        uint32_t hp, lp;
        cvt_pair(z0 * z0, z1 * z1, hp, lp);
        sw[AHo + rA * PA + cp] = hp; sw[ALo + rA * PA + cp] = lp;
        cvt_pair(z2 * z2, z3 * z3, hp, lp);
        sw[AHo + (rA + 8) * PA + cp] = hp; sw[ALo + (rA + 8) * PA + cp] = lp;
    }

    // ================= Phase B: z2 = y1 W2^T + b2 =================
    #pragma unroll
    for (int nt = 0; nt < 16; nt++)
        #pragma unroll
        for (int j = 0; j < 4; j++) dacc[nt][j] = 0.0f;
    for (int kc = 0; kc < 4; kc++) {
        __syncthreads();
        #pragma unroll
        for (int it = 0; it < 32; it++) {
            int combo = it * 8 + wid;
            int n = (combo & 31) * 8 + t4, kp = (combo >> 5) * 4 + q;
            float2 x = *reinterpret_cast<const float2*>(&W2[n * 256 + kc * 64 + 2 * kp]);
            uint32_t hp, lp; cvt_pair(x.x, x.y, hp, lp);
            sw[WHo + n * PW + kp] = hp;
            sw[WLo + n * PW + kp] = lp;
        }
        __syncthreads();
        #pragma unroll
        for (int ks = 0; ks < 4; ks++) {
            int ka = kc * 32 + ks * 8, kb = ks * 8;
            ah[0] = sw[AHo + rA * PA + ka + q];       ah[1] = sw[AHo + (rA + 8) * PA + ka + q];
            ah[2] = sw[AHo + rA * PA + ka + q + 4];   ah[3] = sw[AHo + (rA + 8) * PA + ka + q + 4];
            al[0] = sw[ALo + rA * PA + ka + q];       al[1] = sw[ALo + (rA + 8) * PA + ka + q];
            al[2] = sw[ALo + rA * PA + ka + q + 4];   al[3] = sw[ALo + (rA + 8) * PA + ka + q + 4];
            #pragma unroll
            for (int nt = 0; nt < 16; nt++) {
                int nrow = (nh * 16 + nt) * 8 + t4;
                uint32_t bh0 = sw[WHo + nrow * PW + kb + q], bh1 = sw[WHo + nrow * PW + kb + q + 4];
                uint32_t bl0 = sw[WLo + nrow * PW + kb + q], bl1 = sw[WLo + nrow * PW + kb + q + 4];
                mma_bf16(dacc[nt], ah, bh0, bh1);
                mma_bf16(dacc[nt], ah, bl0, bl1);
                mma_bf16(dacc[nt], al, bh0, bh1);
            }
        }
    }
    __syncthreads();     // y1 reads done before u overwrites
    // ep-B: u = 2*w3*z2 -> ACT ; nn partials
    {
        float pmA = 0.0f, pmB = 0.0f;
        #pragma unroll
        for (int nt = 0; nt < 16; nt++) {
            int c0 = (nh * 16 + nt) * 8 + 2 * q, cp = (nh * 16 + nt) * 4 + q;
            float z0 = dacc[nt][0] + sf[B2o + c0], z1 = dacc[nt][1] + sf[B2o + c0 + 1];
            float z2 = dacc[nt][2] + sf[B2o + c0], z3 = dacc[nt][3] + sf[B2o + c0 + 1];
            float w30 = sf[W3o + c0], w31 = sf[W3o + c0 + 1];
            uint32_t hp, lp;
            cvt_pair(2.0f * w30 * z0, 2.0f * w31 * z1, hp, lp);
            sw[AHo + rA * PA + cp] = hp; sw[ALo + rA * PA + cp] = lp;
            cvt_pair(2.0f * w30 * z2, 2.0f * w31 * z3, hp, lp);
            sw[AHo + (rA + 8) * PA + cp] = hp; sw[ALo + (rA + 8) * PA + cp] = lp;
            pmA = fmaf(w30 * z0, z0, fmaf(w31 * z1, z1, pmA));
            pmB = fmaf(w30 * z2, z2, fmaf(w31 * z3, z3, pmB));
        }
        pmA += __shfl_xor_sync(0xffffffffu, pmA, 1); pmA += __shfl_xor_sync(0xffffffffu, pmA, 2);
        pmB += __shfl_xor_sync(0xffffffffu, pmB, 1); pmB += __shfl_xor_sync(0xffffffffu, pmB, 2);
        if (q == 0) {
            sf[NNo + rA * 2 + nh] = pmA;
            sf[NNo + (rA + 8) * 2 + nh] = pmB;
        }
    }

    // ================= Phase D: t = u W2 =================
    #pragma unroll
    for (int nt = 0; nt < 16; nt++)
        #pragma unroll
        for (int j = 0; j < 4; j++) dacc[nt][j] = 0.0f;
    for (int kc = 0; kc < 4; kc++) {
        __syncthreads();
        #pragma unroll
        for (int it = 0; it < 32; it++) {
            int combo = it * 8 + wid;
            int p = (combo & 31) * 8 + t4, hp_ = (combo >> 5) * 4 + q;
            float lo = W2[(kc * 64 + 2 * hp_) * 256 + p];
            float hi = W2[(kc * 64 + 2 * hp_ + 1) * 256 + p];
            uint32_t hw, lw; cvt_pair(lo, hi, hw, lw);
            sw[WHo + p * PW + hp_] = hw;
            sw[WLo + p * PW + hp_] = lw;
        }
        __syncthreads();
        #pragma unroll
        for (int ks = 0; ks < 4; ks++) {
            int ka = kc * 32 + ks * 8, kb = ks * 8;
            ah[0] = sw[AHo + rA * PA + ka + q];       ah[1] = sw[AHo + (rA + 8) * PA + ka + q];
            ah[2] = sw[AHo + rA * PA + ka + q + 4];   ah[3] = sw[AHo + (rA + 8) * PA + ka + q + 4];
            al[0] = sw[ALo + rA * PA + ka + q];       al[1] = sw[ALo + (rA + 8) * PA + ka + q];
            al[2] = sw[ALo + rA * PA + ka + q + 4];   al[3] = sw[ALo + (rA + 8) * PA + ka + q + 4];
            #pragma unroll
            for (int nt = 0; nt < 16; nt++) {
                int nrow = (nh * 16 + nt) * 8 + t4;
                uint32_t bh0 = sw[WHo + nrow * PW + kb + q], bh1 = sw[WHo + nrow * PW + kb + q + 4];
                uint32_t bl0 = sw[WLo + nrow * PW + kb + q], bl1 = sw[WLo + nrow * PW + kb + q + 4];
                mma_bf16(dacc[nt], ah, bh0, bh1);
                mma_bf16(dacc[nt], ah, bl0, bl1);
                mma_bf16(dacc[nt], al, bh0, bh1);
            }
        }
    }
    __syncthreads();     // u reads done before v overwrites
    // ep-D: v = t * 2*z1 -> ACT
    #pragma unroll
    for (int nt = 0; nt < 16; nt++) {
        int c0 = (nh * 16 + nt) * 8 + 2 * q, cp = (nh * 16 + nt) * 4 + q;
        float2 za = *reinterpret_cast<float2*>(&sf[ZSo + rA * 258 + c0]);
        float2 zb = *reinterpret_cast<float2*>(&sf[ZSo + (rA + 8) * 258 + c0]);
        uint32_t hp, lp;
        cvt_pair(dacc[nt][0] * 2.0f * za.x, dacc[nt][1] * 2.0f * za.y, hp, lp);
        sw[AHo + rA * PA + cp] = hp; sw[ALo + rA * PA + cp] = lp;
        cvt_pair(dacc[nt][2] * 2.0f * zb.x, dacc[nt][3] * 2.0f * zb.y, hp, lp);
        sw[AHo + (rA + 8) * PA + cp] = hp; sw[ALo + (rA + 8) * PA + cp] = lp;
    }
    __syncthreads();

    // ================= Phase E: grad = v W1 (W1^T staged [64 d][128 pp]) =================
    #pragma unroll
    for (int it = 0; it < 32; it++) {
        int combo = it * 8 + wid;
        int d = (combo & 7) * 8 + t4, pp = (combo >> 3) * 4 + q;
        float lo = W1[(2 * pp) * 64 + d];
        float hi = W1[(2 * pp + 1) * 64 + d];
        uint32_t hw, lw; cvt_pair(lo, hi, hw, lw);
        sw[WHo + d * PE + pp] = hw;
        sw[WLo + d * PE + pp] = lw;
    }
    __syncthreads();
    #pragma unroll
    for (int nt = 0; nt < 4; nt++)
        #pragma unroll
        for (int j = 0; j < 4; j++) dacc[nt][j] = 0.0f;
    #pragma unroll
    for (int ks = 0; ks < 16; ks++) {
        int kb = ks * 8;
        ah[0] = sw[AHo + rA * PA + kb + q];       ah[1] = sw[AHo + (rA + 8) * PA + kb + q];
        ah[2] = sw[AHo + rA * PA + kb + q + 4];   ah[3] = sw[AHo + (rA + 8) * PA + kb + q + 4];
        al[0] = sw[ALo + rA * PA + kb + q];       al[1] = sw[ALo + (rA + 8) * PA + kb + q];
        al[2] = sw[ALo + rA * PA + kb + q + 4];   al[3] = sw[ALo + (rA + 8) * PA + kb + q + 4];
        #pragma unroll
        for (int nt = 0; nt < 4; nt++) {
            int nrow = (nh * 4 + nt) * 8 + t4;
            uint32_t bh0 = sw[WHo + nrow * PE + kb + q], bh1 = sw[WHo + nrow * PE + kb + q + 4];
            uint32_t bl0 = sw[WLo + nrow * PE + kb + q], bl1 = sw[WLo + nrow * PE + kb + q + 4];
            mma_bf16(dacc[nt], ah, bh0, bh1);
            mma_bf16(dacc[nt], ah, bl0, bl1);
            mma_bf16(dacc[nt], al, bh0, bh1);
        }
    }
    // ep-E: gd partials (grad . Sdot)
    {
        float gdA = 0.0f, gdB = 0.0f;
        #pragma unroll
        for (int nt = 0; nt < 4; nt++) {
            int cd = (nh * 4 + nt) * 8 + 2 * q;
            float2 sa = *reinterpret_cast<const float2*>(&Sdot[(m0 + rA) * 64 + cd]);
            float2 sb = *reinterpret_cast<const float2*>(&Sdot[(m0 + rA + 8) * 64 + cd]);
            gdA = fmaf(dacc[nt][0], sa.x, fmaf(dacc[nt][1], sa.y, gdA));
            gdB = fmaf(dacc[nt][2], sb.x, fmaf(dacc[nt][3], sb.y, gdB));
        }
        gdA += __shfl_xor_sync(0xffffffffu, gdA, 1); gdA += __shfl_xor_sync(0xffffffffu, gdA, 2);
        gdB += __shfl_xor_sync(0xffffffffu, gdB, 1); gdB += __shfl_xor_sync(0xffffffffu, gdB, 2);
        if (q == 0) {
            sf[GDo + rA * 2 + nh] = gdA;
            sf[GDo + (rA + 8) * 2 + nh] = gdB;
        }
    }
    __syncthreads();

    // ================= Final =================
    {
        int m = tid >> 2, qq = tid & 3;
        float c = 0.0f, sd = 0.0f;
        #pragma unroll
        for (int j = 0; j < 4; j++) {
            float4 s4 = *reinterpret_cast<const float4*>(&S[(m0 + m) * 64 + qq * 16 + 4 * j]);
            float4 t4v = *reinterpret_cast<const float4*>(&Sdot[(m0 + m) * 64 + qq * 16 + 4 * j]);
            c  = fmaf(s4.x, s4.x, fmaf(s4.y, s4.y, fmaf(s4.z, s4.z, fmaf(s4.w, s4.w, c))));
            sd = fmaf(s4.x, t4v.x, fmaf(s4.y, t4v.y, fmaf(s4.z, t4v.z, fmaf(s4.w, t4v.w, sd))));
        }
        c  += __shfl_xor_sync(0xffffffffu, c, 1);  c  += __shfl_xor_sync(0xffffffffu, c, 2);
        sd += __shfl_xor_sync(0xffffffffu, sd, 1); sd += __shfl_xor_sync(0xffffffffu, sd, 2);
        if (qq == 0) {
            float nn = sf[NNo + m * 2] + sf[NNo + m * 2 + 1];
            float gd = sf[GDo + m * 2] + sf[GDo + m * 2 + 1];
            out[m0 + m]              = nn * c;
            out[N_SAMP + m0 + m]     = 2.0f * nn * sd + c * gd;
            out[2 * N_SAMP + m0 + m] = c;
        }
    }
}

extern "C" void kernel_launch(void* const* d_in, const int* in_sizes, int n_in,
                              void* d_out, int out_size)
{
    const float* S    = (const float*)d_in[0];
    const float* Sdot = (const float*)d_in[1];
    const float* W1   = (const float*)d_in[2];
    const float* b1   = (const float*)d_in[3];
    const float* W2   = (const float*)d_in[4];
    const float* b2   = (const float*)d_in[5];
    const float* W3   = (const float*)d_in[6];
    float* out = (float*)d_out;

    cudaFuncSetAttribute(learnerct_mma, cudaFuncAttributeMaxDynamicSharedMemorySize, SMEM_BYTES);
    learnerct_mma<<<NCTA, NT, SMEM_BYTES>>>(S, Sdot, W1, b1, W2, b2, W3, out);
}

// round 12
// speedup vs baseline: 3.0434x; 1.1986x over previous
#include <cuda_runtime.h>
#include <cuda_bf16.h>
#include <cstdint>

#define N_SAMP 16384
#define M_CTA  64
#define NCTA   (N_SAMP / M_CTA)   // 256
#define NT     256

// word offsets
#define ZSo 0        // z1 f32 [64][264]
#define AHo 16896    // ACT hi [64][132]
#define ALo 25344    // ACT lo
#define WHo 33792    // W tile hi [256][36] (A/B/D) or [64][132] (E)
#define WLo 43008    // W tile lo
#define B1o 52224
#define B2o 52480
#define W3o 52736
#define NNo 52992    // [64][4]
#define GDo 53248    // [64][4]
#define SMEM_WORDS 53504
#define SMEM_BYTES (SMEM_WORDS * 4)   // 214016

#define PZ 264
#define PA 132
#define PW 36
#define PE 132

__device__ __forceinline__ void mma_bf16(float d[4], const uint32_t a[4],
                                         uint32_t b0, uint32_t b1) {
    asm volatile(
        "mma.sync.aligned.m16n8k16.row.col.f32.bf16.bf16.f32 "
        "{%0,%1,%2,%3}, {%4,%5,%6,%7}, {%8,%9}, {%0,%1,%2,%3};"
        : "+f"(d[0]), "+f"(d[1]), "+f"(d[2]), "+f"(d[3])
        : "r"(a[0]), "r"(a[1]), "r"(a[2]), "r"(a[3]), "r"(b0), "r"(b1));
}

__device__ __forceinline__ void cvt_pair(float x0, float x1, uint32_t& hp, uint32_t& lp) {
    __nv_bfloat16 h0 = __float2bfloat16_rn(x0);
    __nv_bfloat16 h1 = __float2bfloat16_rn(x1);
    float l0 = x0 - __bfloat162float(h0);
    float l1 = x1 - __bfloat162float(h1);
    __nv_bfloat162 hv(h0, h1), lv(__float2bfloat16_rn(l0), __float2bfloat16_rn(l1));
    hp = *reinterpret_cast<uint32_t*>(&hv);
    lp = *reinterpret_cast<uint32_t*>(&lv);
}

__global__ void __launch_bounds__(NT, 1)
learnerct_mma(const float* __restrict__ S, const float* __restrict__ Sdot,
              const float* __restrict__ W1, const float* __restrict__ b1,
              const float* __restrict__ W2, const float* __restrict__ b2,
              const float* __restrict__ W3, float* __restrict__ out)
{
    extern __shared__ uint32_t sw[];
    float* sf = reinterpret_cast<float*>(sw);
    const int tid = threadIdx.x, lane = tid & 31, wid = tid >> 5;
    const int t4 = lane >> 2, q = lane & 3;
    const int mg = wid & 1;        // m-group: rows mg*32 .. mg*32+31
    const int nq = wid >> 1;       // n-quarter: cols nq*64 .. nq*64+63
    const int m0 = blockIdx.x * M_CTA;

    // ---- stage S -> ACT kp 0..31 ----
    #pragma unroll
    for (int it = 0; it < 8; it++) {
        int fp = it * NT + tid, r = fp >> 5, kp = fp & 31;
        float2 x = *reinterpret_cast<const float2*>(&S[(m0 + r) * 64 + 2 * kp]);
        uint32_t hp, lp; cvt_pair(x.x, x.y, hp, lp);
        sw[AHo + r * PA + kp] = hp;
        sw[ALo + r * PA + kp] = lp;
    }
    // ---- stage W1 [256][32kp] ----
    #pragma unroll
    for (int it = 0; it < 32; it++) {
        int fp = it * NT + tid, n = fp >> 5, kp = fp & 31;
        float2 x = *reinterpret_cast<const float2*>(&W1[n * 64 + 2 * kp]);
        uint32_t hp, lp; cvt_pair(x.x, x.y, hp, lp);
        sw[WHo + n * PW + kp] = hp;
        sw[WLo + n * PW + kp] = lp;
    }
    sf[B1o + tid] = b1[tid];
    sf[B2o + tid] = b2[tid];
    sf[W3o + tid] = W3[tid];
    __syncthreads();

    float dacc[2][8][4];
    uint32_t ahi[2][4], alo[2][4];

    // ================= Phase A: z1 = S W1^T + b1 (K=64) =================
    #pragma unroll
    for (int mf = 0; mf < 2; mf++)
        #pragma unroll
        for (int nt = 0; nt < 8; nt++)
            #pragma unroll
            for (int j = 0; j < 4; j++) dacc[mf][nt][j] = 0.0f;
    #pragma unroll
    for (int ks = 0; ks < 4; ks++) {
        int kb = ks * 8;
        #pragma unroll
        for (int mf = 0; mf < 2; mf++) {
            int r0 = mg * 32 + mf * 16 + t4;
            ahi[mf][0] = sw[AHo + r0 * PA + kb + q];
            ahi[mf][1] = sw[AHo + (r0 + 8) * PA + kb + q];
            ahi[mf][2] = sw[AHo + r0 * PA + kb + q + 4];
            ahi[mf][3] = sw[AHo + (r0 + 8) * PA + kb + q + 4];
            alo[mf][0] = sw[ALo + r0 * PA + kb + q];
            alo[mf][1] = sw[ALo + (r0 + 8) * PA + kb + q];
            alo[mf][2] = sw[ALo + r0 * PA + kb + q + 4];
            alo[mf][3] = sw[ALo + (r0 + 8) * PA + kb + q + 4];
        }
        #pragma unroll
        for (int nt = 0; nt < 8; nt++) {
            int nrow = nq * 64 + nt * 8 + t4;
            uint32_t bh0 = sw[WHo + nrow * PW + kb + q], bh1 = sw[WHo + nrow * PW + kb + q + 4];
            uint32_t bl0 = sw[WLo + nrow * PW + kb + q], bl1 = sw[WLo + nrow * PW + kb + q + 4];
            #pragma unroll
            for (int mf = 0; mf < 2; mf++) {
                mma_bf16(dacc[mf][nt], ahi[mf], bh0, bh1);
                mma_bf16(dacc[mf][nt], ahi[mf], bl0, bl1);
                mma_bf16(dacc[mf][nt], alo[mf], bh0, bh1);
            }
        }
    }
    __syncthreads();   // S reads done before y1 overwrites ACT
    // ep-A: z1 -> ZS, y1 -> ACT
    #pragma unroll
    for (int mf = 0; mf < 2; mf++)
        #pragma unroll
        for (int nt = 0; nt < 8; nt++) {
            int c0 = nq * 64 + nt * 8 + 2 * q, cp = nq * 32 + nt * 4 + q;
            int r0 = mg * 32 + mf * 16 + t4;
            float z0 = dacc[mf][nt][0] + sf[B1o + c0], z1 = dacc[mf][nt][1] + sf[B1o + c0 + 1];
            float z2 = dacc[mf][nt][2] + sf[B1o + c0], z3 = dacc[mf][nt][3] + sf[B1o + c0 + 1];
            *reinterpret_cast<float2*>(&sf[ZSo + r0 * PZ + c0])       = make_float2(z0, z1);
            *reinterpret_cast<float2*>(&sf[ZSo + (r0 + 8) * PZ + c0]) = make_float2(z2, z3);
            uint32_t hp, lp;
            cvt_pair(z0 * z0, z1 * z1, hp, lp);
            sw[AHo + r0 * PA + cp] = hp; sw[ALo + r0 * PA + cp] = lp;
            cvt_pair(z2 * z2, z3 * z3, hp, lp);
            sw[AHo + (r0 + 8) * PA + cp] = hp; sw[ALo + (r0 + 8) * PA + cp] = lp;
        }

    // ================= Phase B: z2 = y1 W2^T + b2 =================
    #pragma unroll
    for (int mf = 0; mf < 2; mf++)
        #pragma unroll
        for (int nt = 0; nt < 8; nt++)
            #pragma unroll
            for (int j = 0; j < 4; j++) dacc[mf][nt][j] = 0.0f;
    for (int kc = 0; kc < 4; kc++) {
        __syncthreads();
        #pragma unroll
        for (int it = 0; it < 32; it++) {
            int fp = it * NT + tid, n = fp >> 5, kp = fp & 31;
            float2 x = *reinterpret_cast<const float2*>(&W2[n * 256 + kc * 64 + 2 * kp]);
            uint32_t hp, lp; cvt_pair(x.x, x.y, hp, lp);
            sw[WHo + n * PW + kp] = hp;
            sw[WLo + n * PW + kp] = lp;
        }
        __syncthreads();
        #pragma unroll
        for (int ks = 0; ks < 4; ks++) {
            int ka = kc * 32 + ks * 8, kb = ks * 8;
            #pragma unroll
            for (int mf = 0; mf < 2; mf++) {
                int r0 = mg * 32 + mf * 16 + t4;
                ahi[mf][0] = sw[AHo + r0 * PA + ka + q];
                ahi[mf][1] = sw[AHo + (r0 + 8) * PA + ka + q];
                ahi[mf][2] = sw[AHo + r0 * PA + ka + q + 4];
                ahi[mf][3] = sw[AHo + (r0 + 8) * PA + ka + q + 4];
                alo[mf][0] = sw[ALo + r0 * PA + ka + q];
                alo[mf][1] = sw[ALo + (r0 + 8) * PA + ka + q];
                alo[mf][2] = sw[ALo + r0 * PA + ka + q + 4];
                alo[mf][3] = sw[ALo + (r0 + 8) * PA + ka + q + 4];
            }
            #pragma unroll
            for (int nt = 0; nt < 8; nt++) {
                int nrow = nq * 64 + nt * 8 + t4;
                uint32_t bh0 = sw[WHo + nrow * PW + kb + q], bh1 = sw[WHo + nrow * PW + kb + q + 4];
                uint32_t bl0 = sw[WLo + nrow * PW + kb + q], bl1 = sw[WLo + nrow * PW + kb + q + 4];
                #pragma unroll
                for (int mf = 0; mf < 2; mf++) {
                    mma_bf16(dacc[mf][nt], ahi[mf], bh0, bh1);
                    mma_bf16(dacc[mf][nt], ahi[mf], bl0, bl1);
                    mma_bf16(dacc[mf][nt], alo[mf], bh0, bh1);
                }
            }
        }
    }
    __syncthreads();   // y1 reads done
    // ep-B: u = 2*w3*z2 -> ACT ; nn partials
    {
        float pm[2][2] = {{0.0f, 0.0f}, {0.0f, 0.0f}};
        #pragma unroll
        for (int mf = 0; mf < 2; mf++)
            #pragma unroll
            for (int nt = 0; nt < 8; nt++) {
                int c0 = nq * 64 + nt * 8 + 2 * q, cp = nq * 32 + nt * 4 + q;
                int r0 = mg * 32 + mf * 16 + t4;
                float z0 = dacc[mf][nt][0] + sf[B2o + c0], z1 = dacc[mf][nt][1] + sf[B2o + c0 + 1];
                float z2 = dacc[mf][nt][2] + sf[B2o + c0], z3 = dacc[mf][nt][3] + sf[B2o + c0 + 1];
                float w30 = sf[W3o + c0], w31 = sf[W3o + c0 + 1];
                uint32_t hp, lp;
                cvt_pair(2.0f * w30 * z0, 2.0f * w31 * z1, hp, lp);
                sw[AHo + r0 * PA + cp] = hp; sw[ALo + r0 * PA + cp] = lp;
                cvt_pair(2.0f * w30 * z2, 2.0f * w31 * z3, hp, lp);
                sw[AHo + (r0 + 8) * PA + cp] = hp; sw[ALo + (r0 + 8) * PA + cp] = lp;
                pm[mf][0] = fmaf(w30 * z0, z0, fmaf(w31 * z1, z1, pm[mf][0]));
                pm[mf][1] = fmaf(w30 * z2, z2, fmaf(w31 * z3, z3, pm[mf][1]));
            }
        #pragma unroll
        for (int mf = 0; mf < 2; mf++)
            #pragma unroll
            for (int h = 0; h < 2; h++) {
                pm[mf][h] += __shfl_xor_sync(0xffffffffu, pm[mf][h], 1);
                pm[mf][h] += __shfl_xor_sync(0xffffffffu, pm[mf][h], 2);
            }
        if (q == 0) {
            #pragma unroll
            for (int mf = 0; mf < 2; mf++)
                #pragma unroll
                for (int h = 0; h < 2; h++)
                    sf[NNo + (mg * 32 + mf * 16 + h * 8 + t4) * 4 + nq] = pm[mf][h];
        }
    }

    // ================= Phase D: t = u W2 =================
    #pragma unroll
    for (int mf = 0; mf < 2; mf++)
        #pragma unroll
        for (int nt = 0; nt < 8; nt++)
            #pragma unroll
            for (int j = 0; j < 4; j++) dacc[mf][nt][j] = 0.0f;
    for (int kc = 0; kc < 4; kc++) {
        __syncthreads();
        #pragma unroll
        for (int it = 0; it < 32; it++) {
            int combo = it * 8 + wid;
            int p = (combo & 31) * 8 + t4, hp_ = (combo >> 5) * 4 + q;
            float lo = W2[(kc * 64 + 2 * hp_) * 256 + p];
            float hi = W2[(kc * 64 + 2 * hp_ + 1) * 256 + p];
            uint32_t hw, lw; cvt_pair(lo, hi, hw, lw);
            sw[WHo + p * PW + hp_] = hw;
            sw[WLo + p * PW + hp_] = lw;
        }
        __syncthreads();
        #pragma unroll
        for (int ks = 0; ks < 4; ks++) {
            int ka = kc * 32 + ks * 8, kb = ks * 8;
            #pragma unroll
            for (int mf = 0; mf < 2; mf++) {
                int r0 = mg * 32 + mf * 16 + t4;
                ahi[mf][0] = sw[AHo + r0 * PA + ka + q];
                ahi[mf][1] = sw[AHo + (r0 + 8) * PA + ka + q];
                ahi[mf][2] = sw[AHo + r0 * PA + ka + q + 4];
                ahi[mf][3] = sw[AHo + (r0 + 8) * PA + ka + q + 4];
                alo[mf][0] = sw[ALo + r0 * PA + ka + q];
                alo[mf][1] = sw[ALo + (r0 + 8) * PA + ka + q];
                alo[mf][2] = sw[ALo + r0 * PA + ka + q + 4];
                alo[mf][3] = sw[ALo + (r0 + 8) * PA + ka + q + 4];
            }
            #pragma unroll
            for (int nt = 0; nt < 8; nt++) {
                int nrow = nq * 64 + nt * 8 + t4;
                uint32_t bh0 = sw[WHo + nrow * PW + kb + q], bh1 = sw[WHo + nrow * PW + kb + q + 4];
                uint32_t bl0 = sw[WLo + nrow * PW + kb + q], bl1 = sw[WLo + nrow * PW + kb + q + 4];
                #pragma unroll
                for (int mf = 0; mf < 2; mf++) {
                    mma_bf16(dacc[mf][nt], ahi[mf], bh0, bh1);
                    mma_bf16(dacc[mf][nt], ahi[mf], bl0, bl1);
                    mma_bf16(dacc[mf][nt], alo[mf], bh0, bh1);
                }
            }
        }
    }
    __syncthreads();   // u reads done
    // ep-D: v = t * 2*z1 -> ACT ; stage E tile (W1^T) concurrently
    #pragma unroll
    for (int mf = 0; mf < 2; mf++)
        #pragma unroll
        for (int nt = 0; nt < 8; nt++) {
            int c0 = nq * 64 + nt * 8 + 2 * q, cp = nq * 32 + nt * 4 + q;
            int r0 = mg * 32 + mf * 16 + t4;
            float2 za = *reinterpret_cast<float2*>(&sf[ZSo + r0 * PZ + c0]);
            float2 zb = *reinterpret_cast<float2*>(&sf[ZSo + (r0 + 8) * PZ + c0]);
            uint32_t hp, lp;
            cvt_pair(dacc[mf][nt][0] * 2.0f * za.x, dacc[mf][nt][1] * 2.0f * za.y, hp, lp);
            sw[AHo + r0 * PA + cp] = hp; sw[ALo + r0 * PA + cp] = lp;
            cvt_pair(dacc[mf][nt][2] * 2.0f * zb.x, dacc[mf][nt][3] * 2.0f * zb.y, hp, lp);
            sw[AHo + (r0 + 8) * PA + cp] = hp; sw[ALo + (r0 + 8) * PA + cp] = lp;
        }
    #pragma unroll
    for (int it = 0; it < 32; it++) {
        int combo = it * 8 + wid;
        int d = (combo & 7) * 8 + t4, pp = (combo >> 3) * 4 + q;
        float lo = W1[(2 * pp) * 64 + d];
        float hi = W1[(2 * pp + 1) * 64 + d];
        uint32_t hw, lw; cvt_pair(lo, hi, hw, lw);
        sw[WHo + d * PE + pp] = hw;
        sw[WLo + d * PE + pp] = lw;
    }
    __syncthreads();

    // ================= Phase E: grad = v W1 =================
    #pragma unroll
    for (int mf = 0; mf < 2; mf++)
        #pragma unroll
        for (int nt = 0; nt < 2; nt++)
            #pragma unroll
            for (int j = 0; j < 4; j++) dacc[mf][nt][j] = 0.0f;
    #pragma unroll
    for (int ks = 0; ks < 16; ks++) {
        int kb = ks * 8;
        #pragma unroll
        for (int mf = 0; mf < 2; mf++) {
            int r0 = mg * 32 + mf * 16 + t4;
            ahi[mf][0] = sw[AHo + r0 * PA + kb + q];
            ahi[mf][1] = sw[AHo + (r0 + 8) * PA + kb + q];
            ahi[mf][2] = sw[AHo + r0 * PA + kb + q + 4];
            ahi[mf][3] = sw[AHo + (r0 + 8) * PA + kb + q + 4];
            alo[mf][0] = sw[ALo + r0 * PA + kb + q];
            alo[mf][1] = sw[ALo + (r0 + 8) * PA + kb + q];
            alo[mf][2] = sw[ALo + r0 * PA + kb + q + 4];
            alo[mf][3] = sw[ALo + (r0 + 8) * PA + kb + q + 4];
        }
        #pragma unroll
        for (int nt = 0; nt < 2; nt++) {
            int nrow = nq * 16 + nt * 8 + t4;
            uint32_t bh0 = sw[WHo + nrow * PE + kb + q], bh1 = sw[WHo + nrow * PE + kb + q + 4];
            uint32_t bl0 = sw[WLo + nrow * PE + kb + q], bl1 = sw[WLo + nrow * PE + kb + q + 4];
            #pragma unroll
            for (int mf = 0; mf < 2; mf++) {
                mma_bf16(dacc[mf][nt], ahi[mf], bh0, bh1);
                mma_bf16(dacc[mf][nt], ahi[mf], bl0, bl1);
                mma_bf16(dacc[mf][nt], alo[mf], bh0, bh1);
            }
        }
    }
    // ep-E: gd partials
    {
        float gd[2][2] = {{0.0f, 0.0f}, {0.0f, 0.0f}};
        #pragma unroll
        for (int mf = 0; mf < 2; mf++)
            #pragma unroll
            for (int nt = 0; nt < 2; nt++) {
                int cd = nq * 16 + nt * 8 + 2 * q;
                int r0 = mg * 32 + mf * 16 + t4;
                float2 sa = *reinterpret_cast<const float2*>(&Sdot[(m0 + r0) * 64 + cd]);
                float2 sb = *reinterpret_cast<const float2*>(&Sdot[(m0 + r0 + 8) * 64 + cd]);
                gd[mf][0] = fmaf(dacc[mf][nt][0], sa.x, fmaf(dacc[mf][nt][1], sa.y, gd[mf][0]));
                gd[mf][1] = fmaf(dacc[mf][nt][2], sb.x, fmaf(dacc[mf][nt][3], sb.y, gd[mf][1]));
            }
        #pragma unroll
        for (int mf = 0; mf < 2; mf++)
            #pragma unroll
            for (int h = 0; h < 2; h++) {
                gd[mf][h] += __shfl_xor_sync(0xffffffffu, gd[mf][h], 1);
                gd[mf][h] += __shfl_xor_sync(0xffffffffu, gd[mf][h], 2);
            }
        if (q == 0) {
            #pragma unroll
            for (int mf = 0; mf < 2; mf++)
                #pragma unroll
                for (int h = 0; h < 2; h++)
                    sf[GDo + (mg * 32 + mf * 16 + h * 8 + t4) * 4 + nq] = gd[mf][h];
        }
    }
    __syncthreads();

    // ================= Final =================
    {
        int m = tid >> 2, qq = tid & 3;
        float c = 0.0f, sd = 0.0f;
        #pragma unroll
        for (int j = 0; j < 4; j++) {
            float4 s4 = *reinterpret_cast<const float4*>(&S[(m0 + m) * 64 + qq * 16 + 4 * j]);
            float4 t4v = *reinterpret_cast<const float4*>(&Sdot[(m0 + m) * 64 + qq * 16 + 4 * j]);
            c  = fmaf(s4.x, s4.x, fmaf(s4.y, s4.y, fmaf(s4.z, s4.z, fmaf(s4.w, s4.w, c))));
            sd = fmaf(s4.x, t4v.x, fmaf(s4.y, t4v.y, fmaf(s4.z, t4v.z, fmaf(s4.w, t4v.w, sd))));
        }
        c  += __shfl_xor_sync(0xffffffffu, c, 1);  c  += __shfl_xor_sync(0xffffffffu, c, 2);
        sd += __shfl_xor_sync(0xffffffffu, sd, 1); sd += __shfl_xor_sync(0xffffffffu, sd, 2);
        if (qq == 0) {
            float nn = sf[NNo + m * 4] + sf[NNo + m * 4 + 1] + sf[NNo + m * 4 + 2] + sf[NNo + m * 4 + 3];
            float gd = sf[GDo + m * 4] + sf[GDo + m * 4 + 1] + sf[GDo + m * 4 + 2] + sf[GDo + m * 4 + 3];
            out[m0 + m]              = nn * c;
            out[N_SAMP + m0 + m]     = 2.0f * nn * sd + c * gd;
            out[2 * N_SAMP + m0 + m] = c;
        }
    }
}

extern "C" void kernel_launch(void* const* d_in, const int* in_sizes, int n_in,
                              void* d_out, int out_size)
{
    const float* S    = (const float*)d_in[0];
    const float* Sdot = (const float*)d_in[1];
    const float* W1   = (const float*)d_in[2];
    const float* b1   = (const float*)d_in[3];
    const float* W2   = (const float*)d_in[4];
    const float* b2   = (const float*)d_in[5];
    const float* W3   = (const float*)d_in[6];
    float* out = (float*)d_out;

    cudaFuncSetAttribute(learnerct_mma, cudaFuncAttributeMaxDynamicSharedMemorySize, SMEM_BYTES);
    learnerct_mma<<<NCTA, NT, SMEM_BYTES>>>(S, Sdot, W1, b1, W2, b2, W3, out);
}